// round 1
// baseline (speedup 1.0000x reference)
#include <cuda_runtime.h>
#include <math.h>

#define BB 2
#define SS 2048
#define DD 1024
#define HH 16
#define HD 64
#define MROWS (BB*SS)   // 4096

// ---------------- scratch (device globals; no allocations allowed) ----------
__device__ float g_Q[BB*HH*SS*HD];
__device__ float g_K[BB*HH*SS*HD];
__device__ float g_V[BB*HH*SS*HD];
__device__ float g_ctx[MROWS*DD];
__device__ float g_bias[HH*SS];      // bias[h][distance], distance = q - k >= 0

// ---------------- bias table: bucket(distance) -> rel_emb lookup ------------
__global__ void bias_table_kernel(const float* __restrict__ rel_emb) {
    int i = blockIdx.x * blockDim.x + threadIdx.x;   // over H*S
    if (i >= HH * SS) return;
    int h = i / SS;
    int d = i % SS;                                   // rp = q - k, >= 0
    int bucket;
    if (d < 16) {
        bucket = d;
    } else {
        // matches: 16 + int( log(rp/16)/log(128/16) * 16 ), clamped to 31
        float v = logf((float)d * (1.0f / 16.0f)) / 2.0794415416798357f * 16.0f;
        bucket = 16 + (int)v;
        if (bucket > 31) bucket = 31;
    }
    g_bias[h * SS + d] = rel_emb[bucket * HH + h];
}

// ---------------- SGEMM: C[4096,1024] = A[4096,1024] @ W[1024,1024] ---------
// headLayout==1: scatter output to [B, H, S, HD] (for Q/K/V)
// headLayout==0: row-major [4096, 1024] (for final projection)
__global__ __launch_bounds__(256) void gemm_kernel(
    const float* __restrict__ A, const float* __restrict__ W,
    float* __restrict__ C, int headLayout)
{
    __shared__ float As[16][64];   // As[k][m] (transposed A tile)
    __shared__ float Bs[16][64];   // Bs[k][n]

    const int tid = threadIdx.x;
    const int tx = tid & 15;
    const int ty = tid >> 4;
    const int m0 = blockIdx.y * 64;
    const int n0 = blockIdx.x * 64;

    float acc[4][4];
#pragma unroll
    for (int i = 0; i < 4; i++)
#pragma unroll
        for (int j = 0; j < 4; j++) acc[i][j] = 0.0f;

    for (int k0 = 0; k0 < DD; k0 += 16) {
        {   // A tile: 64 rows x 16 cols, one float4 per thread, store transposed
            int r  = tid >> 2;
            int c4 = (tid & 3) * 4;
            float4 a = *(const float4*)&A[(size_t)(m0 + r) * DD + k0 + c4];
            As[c4 + 0][r] = a.x; As[c4 + 1][r] = a.y;
            As[c4 + 2][r] = a.z; As[c4 + 3][r] = a.w;
        }
        {   // W tile: 16 rows x 64 cols, one float4 per thread
            int r  = tid >> 4;
            int c4 = (tid & 15) * 4;
            *(float4*)&Bs[r][c4] = *(const float4*)&W[(size_t)(k0 + r) * DD + n0 + c4];
        }
        __syncthreads();

#pragma unroll
        for (int kk = 0; kk < 16; kk++) {
            float4 av = *(const float4*)&As[kk][4 * ty];
            float4 bv = *(const float4*)&Bs[kk][4 * tx];
            float a0 = av.x, a1 = av.y, a2 = av.z, a3 = av.w;
            float b0 = bv.x, b1 = bv.y, b2 = bv.z, b3 = bv.w;
            acc[0][0] += a0 * b0; acc[0][1] += a0 * b1; acc[0][2] += a0 * b2; acc[0][3] += a0 * b3;
            acc[1][0] += a1 * b0; acc[1][1] += a1 * b1; acc[1][2] += a1 * b2; acc[1][3] += a1 * b3;
            acc[2][0] += a2 * b0; acc[2][1] += a2 * b1; acc[2][2] += a2 * b2; acc[2][3] += a2 * b3;
            acc[3][0] += a3 * b0; acc[3][1] += a3 * b1; acc[3][2] += a3 * b2; acc[3][3] += a3 * b3;
        }
        __syncthreads();
    }

    if (!headLayout) {
#pragma unroll
        for (int i = 0; i < 4; i++) {
            int row = m0 + 4 * ty + i;
            float4 v = make_float4(acc[i][0], acc[i][1], acc[i][2], acc[i][3]);
            *(float4*)&C[(size_t)row * DD + n0 + 4 * tx] = v;
        }
    } else {
        int col = n0 + 4 * tx;
        int h   = col >> 6;        // /64
        int hd  = col & 63;
#pragma unroll
        for (int i = 0; i < 4; i++) {
            int m = m0 + 4 * ty + i;
            int b = m >> 11;       // /2048
            int s = m & 2047;
            float4 v = make_float4(acc[i][0], acc[i][1], acc[i][2], acc[i][3]);
            *(float4*)&C[(((size_t)(b * HH + h)) * SS + s) * HD + hd] = v;
        }
    }
}

// ---------------- RoPE applied in-place to Q and K --------------------------
__global__ void rope_kernel() {
    int gid = blockIdx.x * blockDim.x + threadIdx.x;   // B*H*S*32 threads
    int j   = gid & 31;
    int row = gid >> 5;
    if (row >= BB * HH * SS) return;
    int s = row & (SS - 1);

    double inv = pow(10000.0, -(double)j / 32.0);
    double ang = (double)s * inv;
    float c  = (float)cos(ang);
    float sn = (float)sin(ang);

    size_t base = (size_t)row * HD;
    float q0 = g_Q[base + j], q1 = g_Q[base + j + 32];
    g_Q[base + j]      = q0 * c - q1 * sn;
    g_Q[base + j + 32] = q1 * c + q0 * sn;
    float k0 = g_K[base + j], k1 = g_K[base + j + 32];
    g_K[base + j]      = k0 * c - k1 * sn;
    g_K[base + j + 32] = k1 * c + k0 * sn;
}

// ---------------- causal flash attention with relative bias -----------------
// Block: 64 queries for (b, h). 256 threads as 16x16, 4x4 per thread.
#define LDP 65   // padded row stride (words) for shared tiles
__global__ __launch_bounds__(256) void attn_kernel() {
    extern __shared__ float sm[];
    float* Qs    = sm;                 // [64][65]
    float* Ks    = Qs + 64 * LDP;      // [64][65]
    float* Vs    = Ks + 64 * LDP;      // [64][65]
    float* Ps    = Vs + 64 * LDP;      // [64][65]
    float* biasW = Ps + 64 * LDP;      // [128]
    float* m_sh  = biasW + 128;        // [64]
    float* l_sh  = m_sh + 64;          // [64]

    const int tid = threadIdx.x;
    const int tx = tid & 15;
    const int ty = tid >> 4;
    const int qt = blockIdx.x;
    const int h  = blockIdx.y;
    const int b  = blockIdx.z;
    const int q0 = qt * 64;

    const float* Qg = g_Q + (size_t)(b * HH + h) * SS * HD;
    const float* Kg = g_K + (size_t)(b * HH + h) * SS * HD;
    const float* Vg = g_V + (size_t)(b * HH + h) * SS * HD;

    // load Q tile
    for (int i = tid; i < 64 * 16; i += 256) {
        int r  = i >> 4;
        int c4 = (i & 15) * 4;
        float4 v = *(const float4*)&Qg[(size_t)(q0 + r) * HD + c4];
        float* dst = &Qs[r * LDP + c4];
        dst[0] = v.x; dst[1] = v.y; dst[2] = v.z; dst[3] = v.w;
    }
    if (tid < 64) { m_sh[tid] = -1e30f; l_sh[tid] = 0.0f; }

    float o[4][4];
#pragma unroll
    for (int i = 0; i < 4; i++)
#pragma unroll
        for (int j = 0; j < 4; j++) o[i][j] = 0.0f;

    __syncthreads();

    for (int kt = 0; kt <= qt; kt++) {
        const int k0 = kt * 64;
        // load K, V tiles
        for (int i = tid; i < 64 * 16; i += 256) {
            int r  = i >> 4;
            int c4 = (i & 15) * 4;
            float4 kv = *(const float4*)&Kg[(size_t)(k0 + r) * HD + c4];
            float* kd = &Ks[r * LDP + c4];
            kd[0] = kv.x; kd[1] = kv.y; kd[2] = kv.z; kd[3] = kv.w;
            float4 vv = *(const float4*)&Vg[(size_t)(k0 + r) * HD + c4];
            float* vd = &Vs[r * LDP + c4];
            vd[0] = vv.x; vd[1] = vv.y; vd[2] = vv.z; vd[3] = vv.w;
        }
        // bias window: distance d = q - k spans [q0-k0-63, q0-k0+63]
        const int dlo = q0 - k0 - 63;
        if (tid < 128) {
            int d = dlo + tid;
            biasW[tid] = (d >= 0 && d < SS) ? g_bias[h * SS + d] : 0.0f;
        }
        __syncthreads();

        // S = Q K^T (4x4 per thread)
        float s_[4][4];
#pragma unroll
        for (int i = 0; i < 4; i++)
#pragma unroll
            for (int j = 0; j < 4; j++) s_[i][j] = 0.0f;

#pragma unroll 8
        for (int d = 0; d < 64; d++) {
            float qv[4], kv[4];
#pragma unroll
            for (int i = 0; i < 4; i++) qv[i] = Qs[(4 * ty + i) * LDP + d];
#pragma unroll
            for (int j = 0; j < 4; j++) kv[j] = Ks[(4 * tx + j) * LDP + d];
#pragma unroll
            for (int i = 0; i < 4; i++)
#pragma unroll
                for (int j = 0; j < 4; j++) s_[i][j] += qv[i] * kv[j];
        }

        // online softmax (per row, reduce across the 16-lane tx group)
#pragma unroll
        for (int i = 0; i < 4; i++) {
            int r = 4 * ty + i;
            int q = q0 + r;
            float vals[4];
#pragma unroll
            for (int j = 0; j < 4; j++) {
                int k = k0 + 4 * tx + j;
                float v = s_[i][j] * 0.125f + biasW[q - k - dlo];
                vals[j] = (k <= q) ? v : -1e9f;
            }
            float rmax = fmaxf(fmaxf(vals[0], vals[1]), fmaxf(vals[2], vals[3]));
#pragma unroll
            for (int off = 8; off > 0; off >>= 1)
                rmax = fmaxf(rmax, __shfl_xor_sync(0xffffffffu, rmax, off));

            float mold = m_sh[r];
            float mnew = fmaxf(mold, rmax);
            float corr = __expf(mold - mnew);

            float ls = 0.0f;
#pragma unroll
            for (int j = 0; j < 4; j++) {
                float p = __expf(vals[j] - mnew);
                Ps[r * LDP + 4 * tx + j] = p;
                ls += p;
            }
#pragma unroll
            for (int off = 8; off > 0; off >>= 1)
                ls += __shfl_xor_sync(0xffffffffu, ls, off);

#pragma unroll
            for (int j = 0; j < 4; j++) o[i][j] *= corr;

            if (tx == 0) {
                m_sh[r] = mnew;
                l_sh[r] = l_sh[r] * corr + ls;
            }
        }
        __syncthreads();

        // O += P @ V
#pragma unroll 8
        for (int kk = 0; kk < 64; kk++) {
            float pv[4], vv[4];
#pragma unroll
            for (int i = 0; i < 4; i++) pv[i] = Ps[(4 * ty + i) * LDP + kk];
#pragma unroll
            for (int j = 0; j < 4; j++) vv[j] = Vs[kk * LDP + 4 * tx + j];
#pragma unroll
            for (int i = 0; i < 4; i++)
#pragma unroll
                for (int j = 0; j < 4; j++) o[i][j] += pv[i] * vv[j];
        }
        __syncthreads();
    }

    // finalize: ctx[b, q, h*64 + hd] = O / l
#pragma unroll
    for (int i = 0; i < 4; i++) {
        int r = 4 * ty + i;
        int q = q0 + r;
        float inv = 1.0f / l_sh[r];
        float* dst = &g_ctx[((size_t)b * SS + q) * DD + h * HD + 4 * tx];
#pragma unroll
        for (int j = 0; j < 4; j++) dst[j] = o[i][j] * inv;
    }
}

// ---------------- launcher --------------------------------------------------
extern "C" void kernel_launch(void* const* d_in, const int* in_sizes, int n_in,
                              void* d_out, int out_size)
{
    const float* x   = (const float*)d_in[0];
    const float* Wq  = (const float*)d_in[1];
    const float* Wk  = (const float*)d_in[2];
    const float* Wv  = (const float*)d_in[3];
    const float* Wo  = (const float*)d_in[4];
    const float* rel = (const float*)d_in[5];
    float* out = (float*)d_out;

    float *Qb, *Kb, *Vb, *Ctx;
    cudaGetSymbolAddress((void**)&Qb,  g_Q);
    cudaGetSymbolAddress((void**)&Kb,  g_K);
    cudaGetSymbolAddress((void**)&Vb,  g_V);
    cudaGetSymbolAddress((void**)&Ctx, g_ctx);

    const int SMEM = (4 * 64 * LDP + 128 + 64 + 64) * (int)sizeof(float); // ~67.6 KB
    cudaFuncSetAttribute(attn_kernel, cudaFuncAttributeMaxDynamicSharedMemorySize, SMEM);

    // 1) bias table
    bias_table_kernel<<<(HH * SS + 255) / 256, 256>>>(rel);

    // 2) QKV projections (scatter to [B,H,S,HD])
    dim3 gg(DD / 64, MROWS / 64);
    gemm_kernel<<<gg, 256>>>(x, Wq, Qb, 1);
    gemm_kernel<<<gg, 256>>>(x, Wk, Kb, 1);
    gemm_kernel<<<gg, 256>>>(x, Wv, Vb, 1);

    // 3) RoPE on Q and K
    rope_kernel<<<(BB * HH * SS * 32) / 256, 256>>>();

    // 4) causal attention with bias
    attn_kernel<<<dim3(SS / 64, HH, BB), 256, SMEM>>>();

    // 5) output projection
    gemm_kernel<<<gg, 256>>>(Ctx, Wo, out, 0);
}

// round 2
// speedup vs baseline: 1.9076x; 1.9076x over previous
#include <cuda_runtime.h>
#include <math.h>
#include <stdint.h>

#define BB 2
#define SS 2048
#define DD 1024
#define HH 16
#define HD 64
#define MROWS (BB*SS)   // 4096

// ---------------- scratch (device globals; no allocations allowed) ----------
__device__ float g_Q[BB*HH*SS*HD];
__device__ float g_K[BB*HH*SS*HD];
__device__ float g_V[BB*HH*SS*HD];
__device__ float g_ctx[MROWS*DD];
__device__ float g_bias[HH*SS];      // bias[h][distance], distance = q - k >= 0
__device__ float g_cos[SS*32];
__device__ float g_sin[SS*32];

// ---------------- bias table: bucket(distance) -> rel_emb lookup ------------
__global__ void bias_table_kernel(const float* __restrict__ rel_emb) {
    int i = blockIdx.x * blockDim.x + threadIdx.x;   // over H*S
    if (i >= HH * SS) return;
    int h = i / SS;
    int d = i % SS;                                   // rp = q - k, >= 0
    int bucket;
    if (d < 16) {
        bucket = d;
    } else {
        float v = logf((float)d * (1.0f / 16.0f)) / 2.0794415416798357f * 16.0f;
        bucket = 16 + (int)v;
        if (bucket > 31) bucket = 31;
    }
    g_bias[h * SS + d] = rel_emb[bucket * HH + h];
}

// ---------------- RoPE cos/sin table (fp64 once, tiny) ----------------------
__global__ void rope_table_kernel() {
    int i = blockIdx.x * blockDim.x + threadIdx.x;   // SS*32
    if (i >= SS * 32) return;
    int s = i >> 5;
    int j = i & 31;
    double inv = pow(10000.0, -(double)j / 32.0);
    double a = (double)s * inv;
    g_cos[i] = (float)cos(a);
    g_sin[i] = (float)sin(a);
}

// ================= tf32 tensor-core GEMM ====================================
#define GBM 128
#define GBN 128
#define GBK 32
#define LDA 36    // smem A row stride (floats); As[m][k], bank = 4*gid+tig (conflict-free)
#define LDBS 136  // smem B row stride (floats); Bs[k][n], bank = 8*tig+gid (conflict-free)
#define A_TILE (GBM*LDA)   // 4608 floats
#define B_TILE (GBK*LDBS)  // 4352 floats
#define GEMM_SMEM ((A_TILE + B_TILE) * 2 * 4)  // 71680 bytes

__device__ __forceinline__ void cpasync16(uint32_t s, const void* g) {
    asm volatile("cp.async.cg.shared.global [%0], [%1], 16;" :: "r"(s), "l"(g));
}
__device__ __forceinline__ uint32_t f2tf32(float x) {
    uint32_t r;
    asm("cvt.rna.tf32.f32 %0, %1;" : "=r"(r) : "f"(x));
    return r;
}
__device__ __forceinline__ void mma_tf32(float* c, const uint32_t* a, const uint32_t* b) {
    asm volatile(
        "mma.sync.aligned.m16n8k8.row.col.f32.tf32.tf32.f32 "
        "{%0,%1,%2,%3},{%4,%5,%6,%7},{%8,%9},{%0,%1,%2,%3};"
        : "+f"(c[0]), "+f"(c[1]), "+f"(c[2]), "+f"(c[3])
        : "r"(a[0]), "r"(a[1]), "r"(a[2]), "r"(a[3]), "r"(b[0]), "r"(b[1]));
}

__device__ __forceinline__ void gemm_load_stage(
    const float* __restrict__ A, const float* __restrict__ W,
    float* As, float* Bs, int m0, int n0, int k0, int tid)
{
    uint32_t aB = (uint32_t)__cvta_generic_to_shared(As);
    uint32_t bB = (uint32_t)__cvta_generic_to_shared(Bs);
#pragma unroll
    for (int i = 0; i < 4; i++) {       // A tile: 128 rows x 32 cols = 1024 16B segs
        int s = tid * 4 + i;
        int row = s >> 3, cs = s & 7;
        cpasync16(aB + (row * LDA + cs * 4) * 4,
                  A + (size_t)(m0 + row) * DD + k0 + cs * 4);
    }
#pragma unroll
    for (int i = 0; i < 4; i++) {       // B tile: 32 rows x 128 cols = 1024 16B segs
        int s = tid * 4 + i;
        int row = s >> 5, cs = s & 31;
        cpasync16(bB + (row * LDBS + cs * 4) * 4,
                  W + (size_t)(k0 + row) * DD + n0 + cs * 4);
    }
}

__global__ __launch_bounds__(256) void gemm_tc(
    const float* __restrict__ A, const float* __restrict__ W,
    float* __restrict__ C, int headLayout)
{
    extern __shared__ float sm[];
    const int tid  = threadIdx.x;
    const int lane = tid & 31;
    const int wid  = tid >> 5;
    const int gid  = lane >> 2;     // 0..7
    const int tig  = lane & 3;      // 0..3
    const int wm   = (wid >> 2) * 64;
    const int wn   = (wid & 3) * 32;
    const int m0 = blockIdx.y * GBM;
    const int n0 = blockIdx.x * GBN;

    float c[4][4][4];
#pragma unroll
    for (int mt = 0; mt < 4; mt++)
#pragma unroll
        for (int nt = 0; nt < 4; nt++)
#pragma unroll
            for (int i = 0; i < 4; i++) c[mt][nt][i] = 0.0f;

    const int BUF = A_TILE + B_TILE;
    gemm_load_stage(A, W, sm, sm + A_TILE, m0, n0, 0, tid);
    asm volatile("cp.async.commit_group;");

    const int NC = DD / GBK;   // 32
    for (int ch = 0; ch < NC; ch++) {
        if (ch + 1 < NC) {
            float* dst = sm + ((ch + 1) & 1) * BUF;
            gemm_load_stage(A, W, dst, dst + A_TILE, m0, n0, (ch + 1) * GBK, tid);
            asm volatile("cp.async.commit_group;");
            asm volatile("cp.async.wait_group 1;");
        } else {
            asm volatile("cp.async.wait_group 0;");
        }
        __syncthreads();

        const float* Asb = sm + (ch & 1) * BUF;
        const float* Bsb = Asb + A_TILE;

#pragma unroll
        for (int ks = 0; ks < 4; ks++) {
            const int kb = ks * 8;
            uint32_t a[4][4], b[4][2];
#pragma unroll
            for (int mt = 0; mt < 4; mt++) {
                const float* ap = Asb + (wm + mt * 16 + gid) * LDA + kb + tig;
                a[mt][0] = f2tf32(ap[0]);
                a[mt][1] = f2tf32(ap[8 * LDA]);
                a[mt][2] = f2tf32(ap[4]);
                a[mt][3] = f2tf32(ap[8 * LDA + 4]);
            }
#pragma unroll
            for (int nt = 0; nt < 4; nt++) {
                const float* bp = Bsb + (kb + tig) * LDBS + wn + nt * 8 + gid;
                b[nt][0] = f2tf32(bp[0]);
                b[nt][1] = f2tf32(bp[4 * LDBS]);
            }
#pragma unroll
            for (int mt = 0; mt < 4; mt++)
#pragma unroll
                for (int nt = 0; nt < 4; nt++)
                    mma_tf32(c[mt][nt], a[mt], b[nt]);
        }
        __syncthreads();
    }

#pragma unroll
    for (int mt = 0; mt < 4; mt++) {
#pragma unroll
        for (int nt = 0; nt < 4; nt++) {
            int row = m0 + wm + mt * 16 + gid;
            int col = n0 + wn + nt * 8 + 2 * tig;
            float2 v0 = make_float2(c[mt][nt][0], c[mt][nt][1]);
            float2 v1 = make_float2(c[mt][nt][2], c[mt][nt][3]);
            if (!headLayout) {
                *(float2*)&C[(size_t)row * DD + col] = v0;
                *(float2*)&C[(size_t)(row + 8) * DD + col] = v1;
            } else {
                int h = col >> 6, hd = col & 63;
                int b0i = row >> 11, s0 = row & 2047;
                int r1 = row + 8;
                int b1i = r1 >> 11, s1 = r1 & 2047;
                *(float2*)&C[(((size_t)(b0i * HH + h)) * SS + s0) * HD + hd] = v0;
                *(float2*)&C[(((size_t)(b1i * HH + h)) * SS + s1) * HD + hd] = v1;
            }
        }
    }
}

// ---------------- RoPE applied in-place to Q and K (table-driven) -----------
__global__ void rope_kernel() {
    int gid = blockIdx.x * blockDim.x + threadIdx.x;   // B*H*S*32 threads
    int j   = gid & 31;
    int row = gid >> 5;
    if (row >= BB * HH * SS) return;
    int s = row & (SS - 1);

    float c  = g_cos[s * 32 + j];
    float sn = g_sin[s * 32 + j];

    size_t base = (size_t)row * HD;
    float q0 = g_Q[base + j], q1 = g_Q[base + j + 32];
    g_Q[base + j]      = q0 * c - q1 * sn;
    g_Q[base + j + 32] = q1 * c + q0 * sn;
    float k0 = g_K[base + j], k1 = g_K[base + j + 32];
    g_K[base + j]      = k0 * c - k1 * sn;
    g_K[base + j + 32] = k1 * c + k0 * sn;
}

// ---------------- causal flash attention with relative bias -----------------
#define LDP 65
__global__ __launch_bounds__(256) void attn_kernel() {
    extern __shared__ float sm[];
    float* Qs    = sm;
    float* Ks    = Qs + 64 * LDP;
    float* Vs    = Ks + 64 * LDP;
    float* Ps    = Vs + 64 * LDP;
    float* biasW = Ps + 64 * LDP;
    float* m_sh  = biasW + 128;
    float* l_sh  = m_sh + 64;

    const int tid = threadIdx.x;
    const int tx = tid & 15;
    const int ty = tid >> 4;
    const int qt = blockIdx.x;
    const int h  = blockIdx.y;
    const int b  = blockIdx.z;
    const int q0 = qt * 64;

    const float* Qg = g_Q + (size_t)(b * HH + h) * SS * HD;
    const float* Kg = g_K + (size_t)(b * HH + h) * SS * HD;
    const float* Vg = g_V + (size_t)(b * HH + h) * SS * HD;

    for (int i = tid; i < 64 * 16; i += 256) {
        int r  = i >> 4;
        int c4 = (i & 15) * 4;
        float4 v = *(const float4*)&Qg[(size_t)(q0 + r) * HD + c4];
        float* dst = &Qs[r * LDP + c4];
        dst[0] = v.x; dst[1] = v.y; dst[2] = v.z; dst[3] = v.w;
    }
    if (tid < 64) { m_sh[tid] = -1e30f; l_sh[tid] = 0.0f; }

    float o[4][4];
#pragma unroll
    for (int i = 0; i < 4; i++)
#pragma unroll
        for (int j = 0; j < 4; j++) o[i][j] = 0.0f;

    __syncthreads();

    for (int kt = 0; kt <= qt; kt++) {
        const int k0 = kt * 64;
        for (int i = tid; i < 64 * 16; i += 256) {
            int r  = i >> 4;
            int c4 = (i & 15) * 4;
            float4 kv = *(const float4*)&Kg[(size_t)(k0 + r) * HD + c4];
            float* kd = &Ks[r * LDP + c4];
            kd[0] = kv.x; kd[1] = kv.y; kd[2] = kv.z; kd[3] = kv.w;
            float4 vv = *(const float4*)&Vg[(size_t)(k0 + r) * HD + c4];
            float* vd = &Vs[r * LDP + c4];
            vd[0] = vv.x; vd[1] = vv.y; vd[2] = vv.z; vd[3] = vv.w;
        }
        const int dlo = q0 - k0 - 63;
        if (tid < 128) {
            int d = dlo + tid;
            biasW[tid] = (d >= 0 && d < SS) ? g_bias[h * SS + d] : 0.0f;
        }
        __syncthreads();

        float s_[4][4];
#pragma unroll
        for (int i = 0; i < 4; i++)
#pragma unroll
            for (int j = 0; j < 4; j++) s_[i][j] = 0.0f;

#pragma unroll 8
        for (int d = 0; d < 64; d++) {
            float qv[4], kv[4];
#pragma unroll
            for (int i = 0; i < 4; i++) qv[i] = Qs[(4 * ty + i) * LDP + d];
#pragma unroll
            for (int j = 0; j < 4; j++) kv[j] = Ks[(4 * tx + j) * LDP + d];
#pragma unroll
            for (int i = 0; i < 4; i++)
#pragma unroll
                for (int j = 0; j < 4; j++) s_[i][j] += qv[i] * kv[j];
        }

#pragma unroll
        for (int i = 0; i < 4; i++) {
            int r = 4 * ty + i;
            int q = q0 + r;
            float vals[4];
#pragma unroll
            for (int j = 0; j < 4; j++) {
                int k = k0 + 4 * tx + j;
                float v = s_[i][j] * 0.125f + biasW[q - k - dlo];
                vals[j] = (k <= q) ? v : -1e9f;
            }
            float rmax = fmaxf(fmaxf(vals[0], vals[1]), fmaxf(vals[2], vals[3]));
#pragma unroll
            for (int off = 8; off > 0; off >>= 1)
                rmax = fmaxf(rmax, __shfl_xor_sync(0xffffffffu, rmax, off));

            float mold = m_sh[r];
            float mnew = fmaxf(mold, rmax);
            float corr = __expf(mold - mnew);

            float ls = 0.0f;
#pragma unroll
            for (int j = 0; j < 4; j++) {
                float p = __expf(vals[j] - mnew);
                Ps[r * LDP + 4 * tx + j] = p;
                ls += p;
            }
#pragma unroll
            for (int off = 8; off > 0; off >>= 1)
                ls += __shfl_xor_sync(0xffffffffu, ls, off);

#pragma unroll
            for (int j = 0; j < 4; j++) o[i][j] *= corr;

            if (tx == 0) {
                m_sh[r] = mnew;
                l_sh[r] = l_sh[r] * corr + ls;
            }
        }
        __syncthreads();

#pragma unroll 8
        for (int kk = 0; kk < 64; kk++) {
            float pv[4], vv[4];
#pragma unroll
            for (int i = 0; i < 4; i++) pv[i] = Ps[(4 * ty + i) * LDP + kk];
#pragma unroll
            for (int j = 0; j < 4; j++) vv[j] = Vs[kk * LDP + 4 * tx + j];
#pragma unroll
            for (int i = 0; i < 4; i++)
#pragma unroll
                for (int j = 0; j < 4; j++) o[i][j] += pv[i] * vv[j];
        }
        __syncthreads();
    }

#pragma unroll
    for (int i = 0; i < 4; i++) {
        int r = 4 * ty + i;
        int q = q0 + r;
        float inv = 1.0f / l_sh[r];
        float* dst = &g_ctx[((size_t)b * SS + q) * DD + h * HD + 4 * tx];
#pragma unroll
        for (int j = 0; j < 4; j++) dst[j] = o[i][j] * inv;
    }
}

// ---------------- launcher --------------------------------------------------
extern "C" void kernel_launch(void* const* d_in, const int* in_sizes, int n_in,
                              void* d_out, int out_size)
{
    const float* x   = (const float*)d_in[0];
    const float* Wq  = (const float*)d_in[1];
    const float* Wk  = (const float*)d_in[2];
    const float* Wv  = (const float*)d_in[3];
    const float* Wo  = (const float*)d_in[4];
    const float* rel = (const float*)d_in[5];
    float* out = (float*)d_out;

    float *Qb, *Kb, *Vb, *Ctx;
    cudaGetSymbolAddress((void**)&Qb,  g_Q);
    cudaGetSymbolAddress((void**)&Kb,  g_K);
    cudaGetSymbolAddress((void**)&Vb,  g_V);
    cudaGetSymbolAddress((void**)&Ctx, g_ctx);

    const int ATTN_SMEM = (4 * 64 * LDP + 128 + 64 + 64) * (int)sizeof(float);
    cudaFuncSetAttribute(attn_kernel, cudaFuncAttributeMaxDynamicSharedMemorySize, ATTN_SMEM);
    cudaFuncSetAttribute(gemm_tc, cudaFuncAttributeMaxDynamicSharedMemorySize, GEMM_SMEM);

    // 1) setup tables
    bias_table_kernel<<<(HH * SS + 255) / 256, 256>>>(rel);
    rope_table_kernel<<<(SS * 32 + 255) / 256, 256>>>();

    // 2) QKV projections (scatter to [B,H,S,HD])
    dim3 gg(DD / GBN, MROWS / GBM);
    gemm_tc<<<gg, 256, GEMM_SMEM>>>(x, Wq, Qb, 1);
    gemm_tc<<<gg, 256, GEMM_SMEM>>>(x, Wk, Kb, 1);
    gemm_tc<<<gg, 256, GEMM_SMEM>>>(x, Wv, Vb, 1);

    // 3) RoPE on Q and K
    rope_kernel<<<(BB * HH * SS * 32) / 256, 256>>>();

    // 4) causal attention with bias
    attn_kernel<<<dim3(SS / 64, HH, BB), 256, ATTN_SMEM>>>();

    // 5) output projection
    gemm_tc<<<gg, 256, GEMM_SMEM>>>(Ctx, Wo, out, 0);
}

// round 3
// speedup vs baseline: 3.2827x; 1.7208x over previous
#include <cuda_runtime.h>
#include <math.h>
#include <stdint.h>

#define BB 2
#define SS 2048
#define DD 1024
#define HH 16
#define HD 64
#define MROWS (BB*SS)   // 4096

// ---------------- scratch (device globals; no allocations allowed) ----------
__device__ float g_Q[BB*HH*SS*HD];
__device__ float g_K[BB*HH*SS*HD];
__device__ float g_V[BB*HH*SS*HD];
__device__ float g_ctx[MROWS*DD];
__device__ float g_bias[HH*SS];      // bias[h][distance], distance = q - k >= 0
__device__ float g_cos[SS*32];
__device__ float g_sin[SS*32];

// ---------------- common PTX helpers ----------------------------------------
__device__ __forceinline__ void cpasync16(uint32_t s, const void* g) {
    asm volatile("cp.async.cg.shared.global [%0], [%1], 16;" :: "r"(s), "l"(g));
}
__device__ __forceinline__ uint32_t f2tf32(float x) {
    uint32_t r;
    asm("cvt.rna.tf32.f32 %0, %1;" : "=r"(r) : "f"(x));
    return r;
}
__device__ __forceinline__ void mma_tf32(float* c, const uint32_t* a, const uint32_t* b) {
    asm volatile(
        "mma.sync.aligned.m16n8k8.row.col.f32.tf32.tf32.f32 "
        "{%0,%1,%2,%3},{%4,%5,%6,%7},{%8,%9},{%0,%1,%2,%3};"
        : "+f"(c[0]), "+f"(c[1]), "+f"(c[2]), "+f"(c[3])
        : "r"(a[0]), "r"(a[1]), "r"(a[2]), "r"(a[3]), "r"(b[0]), "r"(b[1]));
}

// ---------------- bias table: bucket(distance) -> rel_emb lookup ------------
__global__ void bias_table_kernel(const float* __restrict__ rel_emb) {
    int i = blockIdx.x * blockDim.x + threadIdx.x;   // over H*S
    if (i >= HH * SS) return;
    int h = i / SS;
    int d = i % SS;                                   // rp = q - k, >= 0
    int bucket;
    if (d < 16) {
        bucket = d;
    } else {
        float v = logf((float)d * (1.0f / 16.0f)) / 2.0794415416798357f * 16.0f;
        bucket = 16 + (int)v;
        if (bucket > 31) bucket = 31;
    }
    g_bias[h * SS + d] = rel_emb[bucket * HH + h];
}

// ---------------- RoPE cos/sin table (fp64 once, tiny) ----------------------
__global__ void rope_table_kernel() {
    int i = blockIdx.x * blockDim.x + threadIdx.x;   // SS*32
    if (i >= SS * 32) return;
    int s = i >> 5;
    int j = i & 31;
    double inv = pow(10000.0, -(double)j / 32.0);
    double a = (double)s * inv;
    g_cos[i] = (float)cos(a);
    g_sin[i] = (float)sin(a);
}

// ================= tf32 tensor-core GEMM (unchanged from R2) ================
#define GBM 128
#define GBN 128
#define GBK 32
#define LDA 36
#define LDBS 136
#define A_TILE (GBM*LDA)
#define B_TILE (GBK*LDBS)
#define GEMM_SMEM ((A_TILE + B_TILE) * 2 * 4)

__device__ __forceinline__ void gemm_load_stage(
    const float* __restrict__ A, const float* __restrict__ W,
    float* As, float* Bs, int m0, int n0, int k0, int tid)
{
    uint32_t aB = (uint32_t)__cvta_generic_to_shared(As);
    uint32_t bB = (uint32_t)__cvta_generic_to_shared(Bs);
#pragma unroll
    for (int i = 0; i < 4; i++) {
        int s = tid * 4 + i;
        int row = s >> 3, cs = s & 7;
        cpasync16(aB + (row * LDA + cs * 4) * 4,
                  A + (size_t)(m0 + row) * DD + k0 + cs * 4);
    }
#pragma unroll
    for (int i = 0; i < 4; i++) {
        int s = tid * 4 + i;
        int row = s >> 5, cs = s & 31;
        cpasync16(bB + (row * LDBS + cs * 4) * 4,
                  W + (size_t)(k0 + row) * DD + n0 + cs * 4);
    }
}

__global__ __launch_bounds__(256) void gemm_tc(
    const float* __restrict__ A, const float* __restrict__ W,
    float* __restrict__ C, int headLayout)
{
    extern __shared__ float sm[];
    const int tid  = threadIdx.x;
    const int lane = tid & 31;
    const int wid  = tid >> 5;
    const int gid  = lane >> 2;
    const int tig  = lane & 3;
    const int wm   = (wid >> 2) * 64;
    const int wn   = (wid & 3) * 32;
    const int m0 = blockIdx.y * GBM;
    const int n0 = blockIdx.x * GBN;

    float c[4][4][4];
#pragma unroll
    for (int mt = 0; mt < 4; mt++)
#pragma unroll
        for (int nt = 0; nt < 4; nt++)
#pragma unroll
            for (int i = 0; i < 4; i++) c[mt][nt][i] = 0.0f;

    const int BUF = A_TILE + B_TILE;
    gemm_load_stage(A, W, sm, sm + A_TILE, m0, n0, 0, tid);
    asm volatile("cp.async.commit_group;");

    const int NC = DD / GBK;
    for (int ch = 0; ch < NC; ch++) {
        if (ch + 1 < NC) {
            float* dst = sm + ((ch + 1) & 1) * BUF;
            gemm_load_stage(A, W, dst, dst + A_TILE, m0, n0, (ch + 1) * GBK, tid);
            asm volatile("cp.async.commit_group;");
            asm volatile("cp.async.wait_group 1;");
        } else {
            asm volatile("cp.async.wait_group 0;");
        }
        __syncthreads();

        const float* Asb = sm + (ch & 1) * BUF;
        const float* Bsb = Asb + A_TILE;

#pragma unroll
        for (int ks = 0; ks < 4; ks++) {
            const int kb = ks * 8;
            uint32_t a[4][4], b[4][2];
#pragma unroll
            for (int mt = 0; mt < 4; mt++) {
                const float* ap = Asb + (wm + mt * 16 + gid) * LDA + kb + tig;
                a[mt][0] = f2tf32(ap[0]);
                a[mt][1] = f2tf32(ap[8 * LDA]);
                a[mt][2] = f2tf32(ap[4]);
                a[mt][3] = f2tf32(ap[8 * LDA + 4]);
            }
#pragma unroll
            for (int nt = 0; nt < 4; nt++) {
                const float* bp = Bsb + (kb + tig) * LDBS + wn + nt * 8 + gid;
                b[nt][0] = f2tf32(bp[0]);
                b[nt][1] = f2tf32(bp[4 * LDBS]);
            }
#pragma unroll
            for (int mt = 0; mt < 4; mt++)
#pragma unroll
                for (int nt = 0; nt < 4; nt++)
                    mma_tf32(c[mt][nt], a[mt], b[nt]);
        }
        __syncthreads();
    }

#pragma unroll
    for (int mt = 0; mt < 4; mt++) {
#pragma unroll
        for (int nt = 0; nt < 4; nt++) {
            int row = m0 + wm + mt * 16 + gid;
            int col = n0 + wn + nt * 8 + 2 * tig;
            float2 v0 = make_float2(c[mt][nt][0], c[mt][nt][1]);
            float2 v1 = make_float2(c[mt][nt][2], c[mt][nt][3]);
            if (!headLayout) {
                *(float2*)&C[(size_t)row * DD + col] = v0;
                *(float2*)&C[(size_t)(row + 8) * DD + col] = v1;
            } else {
                int h = col >> 6, hd = col & 63;
                int b0i = row >> 11, s0 = row & 2047;
                int r1 = row + 8;
                int b1i = r1 >> 11, s1 = r1 & 2047;
                *(float2*)&C[(((size_t)(b0i * HH + h)) * SS + s0) * HD + hd] = v0;
                *(float2*)&C[(((size_t)(b1i * HH + h)) * SS + s1) * HD + hd] = v1;
            }
        }
    }
}

// ---------------- RoPE applied in-place to Q and K (table-driven) -----------
__global__ void rope_kernel() {
    int gid = blockIdx.x * blockDim.x + threadIdx.x;
    int j   = gid & 31;
    int row = gid >> 5;
    if (row >= BB * HH * SS) return;
    int s = row & (SS - 1);

    float c  = g_cos[s * 32 + j];
    float sn = g_sin[s * 32 + j];

    size_t base = (size_t)row * HD;
    float q0 = g_Q[base + j], q1 = g_Q[base + j + 32];
    g_Q[base + j]      = q0 * c - q1 * sn;
    g_Q[base + j + 32] = q1 * c + q0 * sn;
    float k0 = g_K[base + j], k1 = g_K[base + j + 32];
    g_K[base + j]      = k0 * c - k1 * sn;
    g_K[base + j + 32] = k1 * c + k0 * sn;
}

// ============== tensor-core causal flash attention ==========================
// BQ=128, BK=64, 256 threads (8 warps x 16 query rows). tf32 mma for QK^T, PV.
#define LDS2 68
#define ATT_K_OFF 0
#define ATT_V_OFF (2*64*LDS2)
#define ATT_P_OFF (4*64*LDS2)
#define ATT_B_OFF (ATT_P_OFF + 128*LDS2)
#define ATT_SMEM ((ATT_B_OFF + 2*192) * 4)   // ~106 KB

__global__ __launch_bounds__(256) void attn_tc() {
    extern __shared__ float sm[];
    float* Ks = sm + ATT_K_OFF;
    float* Vs = sm + ATT_V_OFF;
    float* Ps = sm + ATT_P_OFF;
    float* Bw = sm + ATT_B_OFF;

    const int tid  = threadIdx.x;
    const int lane = tid & 31;
    const int w    = tid >> 5;
    const int gid  = lane >> 2;
    const int tig  = lane & 3;

    const int qt = (gridDim.x - 1) - blockIdx.x;   // long blocks first
    const int h  = blockIdx.y;
    const int b  = blockIdx.z;
    const int q0 = qt * 128;
    const int ktmax = 2 * qt + 1;

    const float* Qg = g_Q + (size_t)(b * HH + h) * SS * HD;
    const float* Kg = g_K + (size_t)(b * HH + h) * SS * HD;
    const float* Vg = g_V + (size_t)(b * HH + h) * SS * HD;
    const float* biasH = g_bias + h * SS;

    const uint32_t smBase = (uint32_t)__cvta_generic_to_shared(sm);

    // ----- prefetch of one K/V tile + bias window (cp.async) -----
    auto prefetch = [&](int kt) {
        const int buf = kt & 1;
        const float* KgT = Kg + (size_t)kt * 64 * HD;
        const float* VgT = Vg + (size_t)kt * 64 * HD;
        uint32_t ka = smBase + (uint32_t)(ATT_K_OFF + buf * 64 * LDS2) * 4;
        uint32_t va = smBase + (uint32_t)(ATT_V_OFF + buf * 64 * LDS2) * 4;
#pragma unroll
        for (int i = 0; i < 4; i++) {
            int s = tid + i * 256;          // 1024 16B segments
            int r = s >> 4, c = (s & 15) * 4;
            cpasync16(ka + (r * LDS2 + c) * 4, KgT + r * HD + c);
            cpasync16(va + (r * LDS2 + c) * 4, VgT + r * HD + c);
        }
        int dlo = q0 - kt * 64 - 63;
        if (tid < 192) {
            int d = dlo + tid;
            int ok = (d >= 0 && d < SS) ? 4 : 0;
            int dc = d < 0 ? 0 : (d >= SS ? SS - 1 : d);
            uint32_t dst = smBase + (uint32_t)(ATT_B_OFF + buf * 192 + tid) * 4;
            asm volatile("cp.async.ca.shared.global [%0], [%1], 4, %2;"
                         :: "r"(dst), "l"(biasH + dc), "r"(ok));
        }
    };

    prefetch(0);
    asm volatile("cp.async.commit_group;");

    // ----- stage Q through Ps, then keep as register fragments -----
#pragma unroll
    for (int i = 0; i < 8; i++) {
        int s = tid + i * 256;              // 2048 16B segments (128 rows x 16)
        int r = s >> 4, c = (s & 15) * 4;
        *(float4*)&Ps[r * LDS2 + c] = *(const float4*)&Qg[(size_t)(q0 + r) * HD + c];
    }
    __syncthreads();

    uint32_t qa[8][4];
#pragma unroll
    for (int kc = 0; kc < 8; kc++) {
        const float* qp = Ps + (16 * w + gid) * LDS2 + kc * 8 + tig;
        qa[kc][0] = f2tf32(qp[0]);
        qa[kc][1] = f2tf32(qp[8 * LDS2]);
        qa[kc][2] = f2tf32(qp[4]);
        qa[kc][3] = f2tf32(qp[8 * LDS2 + 4]);
    }

    float o[8][4];
#pragma unroll
    for (int nt = 0; nt < 8; nt++)
#pragma unroll
        for (int i = 0; i < 4; i++) o[nt][i] = 0.0f;
    float m0 = -1e30f, m1 = -1e30f, l0 = 0.0f, l1 = 0.0f;

    const int qr0 = q0 + 16 * w + gid;      // this thread's first row
    float* pr0 = Ps + (16 * w + gid) * LDS2;
    float* pr1 = pr0 + 8 * LDS2;

    for (int kt = 0; kt <= ktmax; kt++) {
        if (kt < ktmax) {
            prefetch(kt + 1);
            asm volatile("cp.async.commit_group;");
            asm volatile("cp.async.wait_group 1;");
        } else {
            asm volatile("cp.async.wait_group 0;");
        }
        __syncthreads();

        const int k0 = kt * 64;
        const bool active = (k0 <= q0 + 16 * w + 15);   // any valid element?
        if (active) {
            const float* Kb = Ks + (kt & 1) * 64 * LDS2;
            const float* Vb = Vs + (kt & 1) * 64 * LDS2;
            const float* bw = Bw + (kt & 1) * 192;
            const int dlo = q0 - k0 - 63;

            // ---- S = Q K^T ----
            float s_[8][4];
#pragma unroll
            for (int nt = 0; nt < 8; nt++)
#pragma unroll
                for (int i = 0; i < 4; i++) s_[nt][i] = 0.0f;

#pragma unroll
            for (int kc = 0; kc < 8; kc++) {
#pragma unroll
                for (int nt = 0; nt < 8; nt++) {
                    const float* kp = Kb + (nt * 8 + gid) * LDS2 + kc * 8 + tig;
                    uint32_t bf[2] = { f2tf32(kp[0]), f2tf32(kp[4]) };
                    mma_tf32(s_[nt], qa[kc], bf);
                }
            }

            // ---- bias + causal mask + scale; running max ----
            const int r0 = qr0, r1 = qr0 + 8;
            const bool needMask = (k0 + 63 > r0);
            float mx0 = m0, mx1 = m1;
#pragma unroll
            for (int nt = 0; nt < 8; nt++) {
                int c0 = k0 + nt * 8 + 2 * tig;
                s_[nt][0] = s_[nt][0] * 0.125f + bw[r0 - c0 - dlo];
                s_[nt][1] = s_[nt][1] * 0.125f + bw[r0 - c0 - 1 - dlo];
                s_[nt][2] = s_[nt][2] * 0.125f + bw[r1 - c0 - dlo];
                s_[nt][3] = s_[nt][3] * 0.125f + bw[r1 - c0 - 1 - dlo];
                if (needMask) {
                    if (c0     > r0) s_[nt][0] = -1e9f;
                    if (c0 + 1 > r0) s_[nt][1] = -1e9f;
                    if (c0     > r1) s_[nt][2] = -1e9f;
                    if (c0 + 1 > r1) s_[nt][3] = -1e9f;
                }
                mx0 = fmaxf(mx0, fmaxf(s_[nt][0], s_[nt][1]));
                mx1 = fmaxf(mx1, fmaxf(s_[nt][2], s_[nt][3]));
            }
            mx0 = fmaxf(mx0, __shfl_xor_sync(0xffffffffu, mx0, 1));
            mx0 = fmaxf(mx0, __shfl_xor_sync(0xffffffffu, mx0, 2));
            mx1 = fmaxf(mx1, __shfl_xor_sync(0xffffffffu, mx1, 1));
            mx1 = fmaxf(mx1, __shfl_xor_sync(0xffffffffu, mx1, 2));

            float corr0 = __expf(m0 - mx0);
            float corr1 = __expf(m1 - mx1);
            m0 = mx0; m1 = mx1;

            float ls0 = 0.0f, ls1 = 0.0f;
#pragma unroll
            for (int nt = 0; nt < 8; nt++) {
                int c = nt * 8 + 2 * tig;
                float p00 = __expf(s_[nt][0] - mx0);
                float p01 = __expf(s_[nt][1] - mx0);
                float p10 = __expf(s_[nt][2] - mx1);
                float p11 = __expf(s_[nt][3] - mx1);
                ls0 += p00 + p01;
                ls1 += p10 + p11;
                *(float2*)&pr0[c] = make_float2(p00, p01);
                *(float2*)&pr1[c] = make_float2(p10, p11);
                o[nt][0] *= corr0; o[nt][1] *= corr0;
                o[nt][2] *= corr1; o[nt][3] *= corr1;
            }
            ls0 += __shfl_xor_sync(0xffffffffu, ls0, 1);
            ls0 += __shfl_xor_sync(0xffffffffu, ls0, 2);
            ls1 += __shfl_xor_sync(0xffffffffu, ls1, 1);
            ls1 += __shfl_xor_sync(0xffffffffu, ls1, 2);
            l0 = l0 * corr0 + ls0;
            l1 = l1 * corr1 + ls1;
            __syncwarp();

            // ---- O += P V ----
#pragma unroll
            for (int kc = 0; kc < 8; kc++) {
                const float* pp = Ps + (16 * w + gid) * LDS2 + kc * 8 + tig;
                uint32_t pa[4] = { f2tf32(pp[0]), f2tf32(pp[8 * LDS2]),
                                   f2tf32(pp[4]), f2tf32(pp[8 * LDS2 + 4]) };
#pragma unroll
                for (int nt = 0; nt < 8; nt++) {
                    const float* vp = Vb + (kc * 8 + tig) * LDS2 + nt * 8 + gid;
                    uint32_t bf[2] = { f2tf32(vp[0]), f2tf32(vp[4 * LDS2]) };
                    mma_tf32(o[nt], pa, bf);
                }
            }
            __syncwarp();
        }
        __syncthreads();
    }

    // ---- epilogue: ctx[b, q, h*64 + hd] = O / l ----
    const float inv0 = 1.0f / l0;
    const float inv1 = 1.0f / l1;
    const int hbase = h * HD;
#pragma unroll
    for (int nt = 0; nt < 8; nt++) {
        int c = hbase + nt * 8 + 2 * tig;
        *(float2*)&g_ctx[((size_t)b * SS + qr0) * DD + c] =
            make_float2(o[nt][0] * inv0, o[nt][1] * inv0);
        *(float2*)&g_ctx[((size_t)b * SS + qr0 + 8) * DD + c] =
            make_float2(o[nt][2] * inv1, o[nt][3] * inv1);
    }
}

// ---------------- launcher --------------------------------------------------
extern "C" void kernel_launch(void* const* d_in, const int* in_sizes, int n_in,
                              void* d_out, int out_size)
{
    const float* x   = (const float*)d_in[0];
    const float* Wq  = (const float*)d_in[1];
    const float* Wk  = (const float*)d_in[2];
    const float* Wv  = (const float*)d_in[3];
    const float* Wo  = (const float*)d_in[4];
    const float* rel = (const float*)d_in[5];
    float* out = (float*)d_out;

    float *Qb, *Kb, *Vb, *Ctx;
    cudaGetSymbolAddress((void**)&Qb,  g_Q);
    cudaGetSymbolAddress((void**)&Kb,  g_K);
    cudaGetSymbolAddress((void**)&Vb,  g_V);
    cudaGetSymbolAddress((void**)&Ctx, g_ctx);

    cudaFuncSetAttribute(gemm_tc, cudaFuncAttributeMaxDynamicSharedMemorySize, GEMM_SMEM);
    cudaFuncSetAttribute(attn_tc, cudaFuncAttributeMaxDynamicSharedMemorySize, ATT_SMEM);

    // 1) setup tables
    bias_table_kernel<<<(HH * SS + 255) / 256, 256>>>(rel);
    rope_table_kernel<<<(SS * 32 + 255) / 256, 256>>>();

    // 2) QKV projections (scatter to [B,H,S,HD])
    dim3 gg(DD / GBN, MROWS / GBM);
    gemm_tc<<<gg, 256, GEMM_SMEM>>>(x, Wq, Qb, 1);
    gemm_tc<<<gg, 256, GEMM_SMEM>>>(x, Wk, Kb, 1);
    gemm_tc<<<gg, 256, GEMM_SMEM>>>(x, Wv, Vb, 1);

    // 3) RoPE on Q and K
    rope_kernel<<<(BB * HH * SS * 32) / 256, 256>>>();

    // 4) tensor-core causal attention with bias
    attn_tc<<<dim3(SS / 128, HH, BB), 256, ATT_SMEM>>>();

    // 5) output projection
    gemm_tc<<<gg, 256, GEMM_SMEM>>>(Ctx, Wo, out, 0);
}

// round 4
// speedup vs baseline: 3.3900x; 1.0327x over previous
#include <cuda_runtime.h>
#include <math.h>
#include <stdint.h>

#define BB 2
#define SS 2048
#define DD 1024
#define HH 16
#define HD 64
#define MROWS (BB*SS)   // 4096

// ---------------- scratch (device globals; no allocations allowed) ----------
__device__ float g_Q[BB*HH*SS*HD];
__device__ float g_K[BB*HH*SS*HD];
__device__ float g_V[BB*HH*SS*HD];
__device__ float g_ctx[MROWS*DD];
__device__ float g_bias[HH*SS];      // bias[h][distance], distance = q - k >= 0
__device__ float g_cos[SS*32];
__device__ float g_sin[SS*32];
__device__ float g_xc[MROWS*DD];     // tf32-rounded x
__device__ float g_Wc[4*DD*DD];      // tf32-rounded Wq,Wk,Wv,Wo

// ---------------- common PTX helpers ----------------------------------------
__device__ __forceinline__ void cpasync16(uint32_t s, const void* g) {
    asm volatile("cp.async.cg.shared.global [%0], [%1], 16;" :: "r"(s), "l"(g));
}
__device__ __forceinline__ uint32_t f2tf32(float x) {
    uint32_t r;
    asm("cvt.rna.tf32.f32 %0, %1;" : "=r"(r) : "f"(x));
    return r;
}
__device__ __forceinline__ float rnd_tf32(float x) {
    return __uint_as_float(f2tf32(x));
}
__device__ __forceinline__ void mma_tf32(float* c, const uint32_t* a, const uint32_t* b) {
    asm volatile(
        "mma.sync.aligned.m16n8k8.row.col.f32.tf32.tf32.f32 "
        "{%0,%1,%2,%3},{%4,%5,%6,%7},{%8,%9},{%0,%1,%2,%3};"
        : "+f"(c[0]), "+f"(c[1]), "+f"(c[2]), "+f"(c[3])
        : "r"(a[0]), "r"(a[1]), "r"(a[2]), "r"(a[3]), "r"(b[0]), "r"(b[1]));
}

// ---------------- tf32 pre-rounding pass ------------------------------------
__global__ void round_tf32_kernel(const float* __restrict__ src,
                                  float* __restrict__ dst, int n) {
    int i = (blockIdx.x * blockDim.x + threadIdx.x) * 4;
    if (i >= n) return;
    float4 v = *(const float4*)(src + i);
    v.x = rnd_tf32(v.x); v.y = rnd_tf32(v.y);
    v.z = rnd_tf32(v.z); v.w = rnd_tf32(v.w);
    *(float4*)(dst + i) = v;
}

// ---------------- bias table: bucket(distance) -> rel_emb lookup ------------
__global__ void bias_table_kernel(const float* __restrict__ rel_emb) {
    int i = blockIdx.x * blockDim.x + threadIdx.x;   // over H*S
    if (i >= HH * SS) return;
    int h = i / SS;
    int d = i % SS;
    int bucket;
    if (d < 16) {
        bucket = d;
    } else {
        float v = logf((float)d * (1.0f / 16.0f)) / 2.0794415416798357f * 16.0f;
        bucket = 16 + (int)v;
        if (bucket > 31) bucket = 31;
    }
    g_bias[h * SS + d] = rel_emb[bucket * HH + h];
}

// ---------------- RoPE cos/sin table (fp64 once, tiny) ----------------------
__global__ void rope_table_kernel() {
    int i = blockIdx.x * blockDim.x + threadIdx.x;   // SS*32
    if (i >= SS * 32) return;
    int s = i >> 5;
    int j = i & 31;
    double inv = pow(10000.0, -(double)j / 32.0);
    double a = (double)s * inv;
    g_cos[i] = (float)cos(a);
    g_sin[i] = (float)sin(a);
}

// ================= tf32 tensor-core GEMM core ===============================
#define GBM 128
#define GBN 128
#define GBK 32
#define LDA 36
#define LDBS 136
#define A_TILE (GBM*LDA)
#define B_TILE (GBK*LDBS)
#define GEMM_SMEM ((A_TILE + B_TILE) * 2 * 4)

__device__ __forceinline__ void gemm_load_stage(
    const float* __restrict__ A, const float* __restrict__ W,
    float* As, float* Bs, int m0, int n0, int k0, int tid)
{
    uint32_t aB = (uint32_t)__cvta_generic_to_shared(As);
    uint32_t bB = (uint32_t)__cvta_generic_to_shared(Bs);
#pragma unroll
    for (int i = 0; i < 4; i++) {
        int s = tid * 4 + i;
        int row = s >> 3, cs = s & 7;
        cpasync16(aB + (row * LDA + cs * 4) * 4,
                  A + (size_t)(m0 + row) * DD + k0 + cs * 4);
    }
#pragma unroll
    for (int i = 0; i < 4; i++) {
        int s = tid * 4 + i;
        int row = s >> 5, cs = s & 31;
        cpasync16(bB + (row * LDBS + cs * 4) * 4,
                  W + (size_t)(k0 + row) * DD + n0 + cs * 4);
    }
}

// gemm body: inputs pre-rounded to tf32, so fragments are raw bit loads.
__device__ __forceinline__ void gemm_body(
    const float* __restrict__ A, const float* __restrict__ W,
    float* __restrict__ C, int headLayout, float* sm)
{
    const int tid  = threadIdx.x;
    const int lane = tid & 31;
    const int wid  = tid >> 5;
    const int gid  = lane >> 2;
    const int tig  = lane & 3;
    const int wm   = (wid >> 2) * 64;
    const int wn   = (wid & 3) * 32;
    const int m0 = blockIdx.y * GBM;
    const int n0 = blockIdx.x * GBN;

    float c[4][4][4];
#pragma unroll
    for (int mt = 0; mt < 4; mt++)
#pragma unroll
        for (int nt = 0; nt < 4; nt++)
#pragma unroll
            for (int i = 0; i < 4; i++) c[mt][nt][i] = 0.0f;

    const int BUF = A_TILE + B_TILE;
    gemm_load_stage(A, W, sm, sm + A_TILE, m0, n0, 0, tid);
    asm volatile("cp.async.commit_group;");

    const int NC = DD / GBK;
    for (int ch = 0; ch < NC; ch++) {
        if (ch + 1 < NC) {
            float* dst = sm + ((ch + 1) & 1) * BUF;
            gemm_load_stage(A, W, dst, dst + A_TILE, m0, n0, (ch + 1) * GBK, tid);
            asm volatile("cp.async.commit_group;");
            asm volatile("cp.async.wait_group 1;");
        } else {
            asm volatile("cp.async.wait_group 0;");
        }
        __syncthreads();

        const uint32_t* Asb = (const uint32_t*)(sm + (ch & 1) * BUF);
        const uint32_t* Bsb = Asb + A_TILE;

#pragma unroll
        for (int ks = 0; ks < 4; ks++) {
            const int kb = ks * 8;
            uint32_t a[4][4], b[4][2];
#pragma unroll
            for (int mt = 0; mt < 4; mt++) {
                const uint32_t* ap = Asb + (wm + mt * 16 + gid) * LDA + kb + tig;
                a[mt][0] = ap[0];
                a[mt][1] = ap[8 * LDA];
                a[mt][2] = ap[4];
                a[mt][3] = ap[8 * LDA + 4];
            }
#pragma unroll
            for (int nt = 0; nt < 4; nt++) {
                const uint32_t* bp = Bsb + (kb + tig) * LDBS + wn + nt * 8 + gid;
                b[nt][0] = bp[0];
                b[nt][1] = bp[4 * LDBS];
            }
#pragma unroll
            for (int mt = 0; mt < 4; mt++)
#pragma unroll
                for (int nt = 0; nt < 4; nt++)
                    mma_tf32(c[mt][nt], a[mt], b[nt]);
        }
        __syncthreads();
    }

#pragma unroll
    for (int mt = 0; mt < 4; mt++) {
#pragma unroll
        for (int nt = 0; nt < 4; nt++) {
            int row = m0 + wm + mt * 16 + gid;
            int col = n0 + wn + nt * 8 + 2 * tig;
            float2 v0 = make_float2(c[mt][nt][0], c[mt][nt][1]);
            float2 v1 = make_float2(c[mt][nt][2], c[mt][nt][3]);
            if (!headLayout) {
                *(float2*)&C[(size_t)row * DD + col] = v0;
                *(float2*)&C[(size_t)(row + 8) * DD + col] = v1;
            } else {
                int h = col >> 6, hd = col & 63;
                int b0i = row >> 11, s0 = row & 2047;
                int r1 = row + 8;
                int b1i = r1 >> 11, s1 = r1 & 2047;
                *(float2*)&C[(((size_t)(b0i * HH + h)) * SS + s0) * HD + hd] = v0;
                *(float2*)&C[(((size_t)(b1i * HH + h)) * SS + s1) * HD + hd] = v1;
            }
        }
    }
}

// fused QKV projection: blockIdx.z selects weight + destination
__global__ __launch_bounds__(256) void gemm_qkv() {
    extern __shared__ float sm[];
    const int z = blockIdx.z;
    const float* W = g_Wc + (size_t)z * DD * DD;
    float* C = (z == 0) ? g_Q : (z == 1) ? g_K : g_V;
    gemm_body(g_xc, W, C, 1, sm);
}

// output projection
__global__ __launch_bounds__(256) void gemm_out(float* __restrict__ out) {
    extern __shared__ float sm[];
    gemm_body(g_ctx, g_Wc + (size_t)3 * DD * DD, out, 0, sm);
}

// ---------------- RoPE in-place on Q,K + tf32 rounding of Q,K,V -------------
__global__ void rope_kernel() {
    int gid = blockIdx.x * blockDim.x + threadIdx.x;
    int j   = gid & 31;
    int row = gid >> 5;
    if (row >= BB * HH * SS) return;
    int s = row & (SS - 1);

    float c  = g_cos[s * 32 + j];
    float sn = g_sin[s * 32 + j];

    size_t base = (size_t)row * HD;
    float q0 = g_Q[base + j], q1 = g_Q[base + j + 32];
    g_Q[base + j]      = rnd_tf32(q0 * c - q1 * sn);
    g_Q[base + j + 32] = rnd_tf32(q1 * c + q0 * sn);
    float k0 = g_K[base + j], k1 = g_K[base + j + 32];
    g_K[base + j]      = rnd_tf32(k0 * c - k1 * sn);
    g_K[base + j + 32] = rnd_tf32(k1 * c + k0 * sn);
    g_V[base + j]      = rnd_tf32(g_V[base + j]);
    g_V[base + j + 32] = rnd_tf32(g_V[base + j + 32]);
}

// ============== tensor-core causal flash attention ==========================
// BQ=128, BK=64, 256 threads (8 warps x 16 query rows). tf32 mma for QK^T, PV.
// Q/K/V pre-rounded to tf32 -> fragment loads are raw bit loads.
#define LDS2 68
#define ATT_K_OFF 0
#define ATT_V_OFF (2*64*LDS2)
#define ATT_P_OFF (4*64*LDS2)
#define ATT_B_OFF (ATT_P_OFF + 128*LDS2)
#define ATT_SMEM ((ATT_B_OFF + 2*192) * 4)   // ~106 KB

__global__ __launch_bounds__(256) void attn_tc() {
    extern __shared__ float sm[];
    float* Ks = sm + ATT_K_OFF;
    float* Vs = sm + ATT_V_OFF;
    float* Ps = sm + ATT_P_OFF;
    float* Bw = sm + ATT_B_OFF;

    const int tid  = threadIdx.x;
    const int lane = tid & 31;
    const int w    = tid >> 5;
    const int gid  = lane >> 2;
    const int tig  = lane & 3;

    const int qt = (gridDim.x - 1) - blockIdx.x;   // long blocks first
    const int h  = blockIdx.y;
    const int b  = blockIdx.z;
    const int q0 = qt * 128;
    const int ktmax = 2 * qt + 1;

    const float* Qg = g_Q + (size_t)(b * HH + h) * SS * HD;
    const float* Kg = g_K + (size_t)(b * HH + h) * SS * HD;
    const float* Vg = g_V + (size_t)(b * HH + h) * SS * HD;
    const float* biasH = g_bias + h * SS;

    const uint32_t smBase = (uint32_t)__cvta_generic_to_shared(sm);

    auto prefetch = [&](int kt) {
        const int buf = kt & 1;
        const float* KgT = Kg + (size_t)kt * 64 * HD;
        const float* VgT = Vg + (size_t)kt * 64 * HD;
        uint32_t ka = smBase + (uint32_t)(ATT_K_OFF + buf * 64 * LDS2) * 4;
        uint32_t va = smBase + (uint32_t)(ATT_V_OFF + buf * 64 * LDS2) * 4;
#pragma unroll
        for (int i = 0; i < 4; i++) {
            int s = tid + i * 256;
            int r = s >> 4, c = (s & 15) * 4;
            cpasync16(ka + (r * LDS2 + c) * 4, KgT + r * HD + c);
            cpasync16(va + (r * LDS2 + c) * 4, VgT + r * HD + c);
        }
        int dlo = q0 - kt * 64 - 63;
        if (tid < 192) {
            int d = dlo + tid;
            int ok = (d >= 0 && d < SS) ? 4 : 0;
            int dc = d < 0 ? 0 : (d >= SS ? SS - 1 : d);
            uint32_t dst = smBase + (uint32_t)(ATT_B_OFF + buf * 192 + tid) * 4;
            asm volatile("cp.async.ca.shared.global [%0], [%1], 4, %2;"
                         :: "r"(dst), "l"(biasH + dc), "r"(ok));
        }
    };

    prefetch(0);
    asm volatile("cp.async.commit_group;");

    // stage Q through Ps, keep as register fragments (already tf32-rounded)
#pragma unroll
    for (int i = 0; i < 8; i++) {
        int s = tid + i * 256;
        int r = s >> 4, c = (s & 15) * 4;
        *(float4*)&Ps[r * LDS2 + c] = *(const float4*)&Qg[(size_t)(q0 + r) * HD + c];
    }
    __syncthreads();

    uint32_t qa[8][4];
#pragma unroll
    for (int kc = 0; kc < 8; kc++) {
        const uint32_t* qp = (const uint32_t*)(Ps + (16 * w + gid) * LDS2 + kc * 8 + tig);
        qa[kc][0] = qp[0];
        qa[kc][1] = qp[8 * LDS2];
        qa[kc][2] = qp[4];
        qa[kc][3] = qp[8 * LDS2 + 4];
    }

    float o[8][4];
#pragma unroll
    for (int nt = 0; nt < 8; nt++)
#pragma unroll
        for (int i = 0; i < 4; i++) o[nt][i] = 0.0f;
    float m0 = -1e30f, m1 = -1e30f, l0 = 0.0f, l1 = 0.0f;

    const int qr0 = q0 + 16 * w + gid;
    float* pr0 = Ps + (16 * w + gid) * LDS2;
    float* pr1 = pr0 + 8 * LDS2;

    for (int kt = 0; kt <= ktmax; kt++) {
        if (kt < ktmax) {
            prefetch(kt + 1);
            asm volatile("cp.async.commit_group;");
            asm volatile("cp.async.wait_group 1;");
        } else {
            asm volatile("cp.async.wait_group 0;");
        }
        __syncthreads();

        const int k0 = kt * 64;
        const bool active = (k0 <= q0 + 16 * w + 15);
        if (active) {
            const uint32_t* Kb = (const uint32_t*)(Ks + (kt & 1) * 64 * LDS2);
            const uint32_t* Vb = (const uint32_t*)(Vs + (kt & 1) * 64 * LDS2);
            const float* bw = Bw + (kt & 1) * 192;
            const int dlo = q0 - k0 - 63;

            // ---- S = Q K^T ----
            float s_[8][4];
#pragma unroll
            for (int nt = 0; nt < 8; nt++)
#pragma unroll
                for (int i = 0; i < 4; i++) s_[nt][i] = 0.0f;

#pragma unroll
            for (int kc = 0; kc < 8; kc++) {
#pragma unroll
                for (int nt = 0; nt < 8; nt++) {
                    const uint32_t* kp = Kb + (nt * 8 + gid) * LDS2 + kc * 8 + tig;
                    uint32_t bf[2] = { kp[0], kp[4] };
                    mma_tf32(s_[nt], qa[kc], bf);
                }
            }

            // ---- bias + causal mask + scale; running max ----
            const int r0 = qr0, r1 = qr0 + 8;
            const bool needMask = (k0 + 63 > r0);
            float mx0 = m0, mx1 = m1;
#pragma unroll
            for (int nt = 0; nt < 8; nt++) {
                int c0 = k0 + nt * 8 + 2 * tig;
                s_[nt][0] = s_[nt][0] * 0.125f + bw[r0 - c0 - dlo];
                s_[nt][1] = s_[nt][1] * 0.125f + bw[r0 - c0 - 1 - dlo];
                s_[nt][2] = s_[nt][2] * 0.125f + bw[r1 - c0 - dlo];
                s_[nt][3] = s_[nt][3] * 0.125f + bw[r1 - c0 - 1 - dlo];
                if (needMask) {
                    if (c0     > r0) s_[nt][0] = -1e9f;
                    if (c0 + 1 > r0) s_[nt][1] = -1e9f;
                    if (c0     > r1) s_[nt][2] = -1e9f;
                    if (c0 + 1 > r1) s_[nt][3] = -1e9f;
                }
                mx0 = fmaxf(mx0, fmaxf(s_[nt][0], s_[nt][1]));
                mx1 = fmaxf(mx1, fmaxf(s_[nt][2], s_[nt][3]));
            }
            mx0 = fmaxf(mx0, __shfl_xor_sync(0xffffffffu, mx0, 1));
            mx0 = fmaxf(mx0, __shfl_xor_sync(0xffffffffu, mx0, 2));
            mx1 = fmaxf(mx1, __shfl_xor_sync(0xffffffffu, mx1, 1));
            mx1 = fmaxf(mx1, __shfl_xor_sync(0xffffffffu, mx1, 2));

            float corr0 = __expf(m0 - mx0);
            float corr1 = __expf(m1 - mx1);
            m0 = mx0; m1 = mx1;

            float ls0 = 0.0f, ls1 = 0.0f;
#pragma unroll
            for (int nt = 0; nt < 8; nt++) {
                int c = nt * 8 + 2 * tig;
                float p00 = __expf(s_[nt][0] - mx0);
                float p01 = __expf(s_[nt][1] - mx0);
                float p10 = __expf(s_[nt][2] - mx1);
                float p11 = __expf(s_[nt][3] - mx1);
                ls0 += p00 + p01;
                ls1 += p10 + p11;
                *(float2*)&pr0[c] = make_float2(p00, p01);
                *(float2*)&pr1[c] = make_float2(p10, p11);
                o[nt][0] *= corr0; o[nt][1] *= corr0;
                o[nt][2] *= corr1; o[nt][3] *= corr1;
            }
            ls0 += __shfl_xor_sync(0xffffffffu, ls0, 1);
            ls0 += __shfl_xor_sync(0xffffffffu, ls0, 2);
            ls1 += __shfl_xor_sync(0xffffffffu, ls1, 1);
            ls1 += __shfl_xor_sync(0xffffffffu, ls1, 2);
            l0 = l0 * corr0 + ls0;
            l1 = l1 * corr1 + ls1;
            __syncwarp();

            // ---- O += P V ----
#pragma unroll
            for (int kc = 0; kc < 8; kc++) {
                const float* pp = Ps + (16 * w + gid) * LDS2 + kc * 8 + tig;
                uint32_t pa[4] = { f2tf32(pp[0]), f2tf32(pp[8 * LDS2]),
                                   f2tf32(pp[4]), f2tf32(pp[8 * LDS2 + 4]) };
#pragma unroll
                for (int nt = 0; nt < 8; nt++) {
                    const uint32_t* vp = Vb + (kc * 8 + tig) * LDS2 + nt * 8 + gid;
                    uint32_t bf[2] = { vp[0], vp[4 * LDS2] };
                    mma_tf32(o[nt], pa, bf);
                }
            }
            __syncwarp();
        }
        __syncthreads();
    }

    // epilogue: ctx rounded to tf32 (feeds Wo GEMM)
    const float inv0 = 1.0f / l0;
    const float inv1 = 1.0f / l1;
    const int hbase = h * HD;
#pragma unroll
    for (int nt = 0; nt < 8; nt++) {
        int c = hbase + nt * 8 + 2 * tig;
        *(float2*)&g_ctx[((size_t)b * SS + qr0) * DD + c] =
            make_float2(rnd_tf32(o[nt][0] * inv0), rnd_tf32(o[nt][1] * inv0));
        *(float2*)&g_ctx[((size_t)b * SS + qr0 + 8) * DD + c] =
            make_float2(rnd_tf32(o[nt][2] * inv1), rnd_tf32(o[nt][3] * inv1));
    }
}

// ---------------- launcher --------------------------------------------------
extern "C" void kernel_launch(void* const* d_in, const int* in_sizes, int n_in,
                              void* d_out, int out_size)
{
    const float* x   = (const float*)d_in[0];
    const float* Wq  = (const float*)d_in[1];
    const float* Wk  = (const float*)d_in[2];
    const float* Wv  = (const float*)d_in[3];
    const float* Wo  = (const float*)d_in[4];
    const float* rel = (const float*)d_in[5];
    float* out = (float*)d_out;

    float *xc, *Wc;
    cudaGetSymbolAddress((void**)&xc, g_xc);
    cudaGetSymbolAddress((void**)&Wc, g_Wc);

    cudaFuncSetAttribute(gemm_qkv, cudaFuncAttributeMaxDynamicSharedMemorySize, GEMM_SMEM);
    cudaFuncSetAttribute(gemm_out, cudaFuncAttributeMaxDynamicSharedMemorySize, GEMM_SMEM);
    cudaFuncSetAttribute(attn_tc, cudaFuncAttributeMaxDynamicSharedMemorySize, ATT_SMEM);

    // 1) setup tables + tf32 pre-rounding of inputs
    bias_table_kernel<<<(HH * SS + 255) / 256, 256>>>(rel);
    rope_table_kernel<<<(SS * 32 + 255) / 256, 256>>>();
    round_tf32_kernel<<<(MROWS * DD / 4 + 255) / 256, 256>>>(x, xc, MROWS * DD);
    round_tf32_kernel<<<(DD * DD / 4 + 255) / 256, 256>>>(Wq, Wc + 0 * DD * DD, DD * DD);
    round_tf32_kernel<<<(DD * DD / 4 + 255) / 256, 256>>>(Wk, Wc + 1 * DD * DD, DD * DD);
    round_tf32_kernel<<<(DD * DD / 4 + 255) / 256, 256>>>(Wv, Wc + 2 * DD * DD, DD * DD);
    round_tf32_kernel<<<(DD * DD / 4 + 255) / 256, 256>>>(Wo, Wc + 3 * DD * DD, DD * DD);

    // 2) fused QKV projections (scatter to [B,H,S,HD])
    gemm_qkv<<<dim3(DD / GBN, MROWS / GBM, 3), 256, GEMM_SMEM>>>();

    // 3) RoPE on Q,K (+ tf32 rounding of Q,K,V)
    rope_kernel<<<(BB * HH * SS * 32) / 256, 256>>>();

    // 4) tensor-core causal attention with bias
    attn_tc<<<dim3(SS / 128, HH, BB), 256, ATT_SMEM>>>();

    // 5) output projection
    gemm_out<<<dim3(DD / GBN, MROWS / GBM), 256, GEMM_SMEM>>>(out);
}

// round 5
// speedup vs baseline: 3.4470x; 1.0168x over previous
#include <cuda_runtime.h>
#include <math.h>
#include <stdint.h>

#define BB 2
#define SS 2048
#define DD 1024
#define HH 16
#define HD 64
#define MROWS (BB*SS)   // 4096

// ---------------- scratch (device globals; no allocations allowed) ----------
__device__ float g_Q[BB*HH*SS*HD];
__device__ float g_K[BB*HH*SS*HD];
__device__ float g_V[BB*HH*SS*HD];
__device__ float g_ctx[MROWS*DD];
__device__ float g_bias[HH*SS];      // bias[h][distance], distance = q - k >= 0
__device__ float g_cos[SS*32];
__device__ float g_sin[SS*32];
__device__ float g_xc[MROWS*DD];     // tf32-rounded x
__device__ float g_Wc[4*DD*DD];      // tf32-rounded Wq,Wk,Wv,Wo

// ---------------- common PTX helpers ----------------------------------------
__device__ __forceinline__ void cpasync16(uint32_t s, const void* g) {
    asm volatile("cp.async.cg.shared.global [%0], [%1], 16;" :: "r"(s), "l"(g));
}
__device__ __forceinline__ uint32_t f2tf32(float x) {
    uint32_t r;
    asm("cvt.rna.tf32.f32 %0, %1;" : "=r"(r) : "f"(x));
    return r;
}
__device__ __forceinline__ float rnd_tf32(float x) {
    return __uint_as_float(f2tf32(x));
}
__device__ __forceinline__ void mma_tf32(float* c, const uint32_t* a, const uint32_t* b) {
    asm volatile(
        "mma.sync.aligned.m16n8k8.row.col.f32.tf32.tf32.f32 "
        "{%0,%1,%2,%3},{%4,%5,%6,%7},{%8,%9},{%0,%1,%2,%3};"
        : "+f"(c[0]), "+f"(c[1]), "+f"(c[2]), "+f"(c[3])
        : "r"(a[0]), "r"(a[1]), "r"(a[2]), "r"(a[3]), "r"(b[0]), "r"(b[1]));
}

// ---------------- tf32 pre-rounding pass ------------------------------------
__global__ void round_tf32_kernel(const float* __restrict__ src,
                                  float* __restrict__ dst, int n) {
    int i = (blockIdx.x * blockDim.x + threadIdx.x) * 4;
    if (i >= n) return;
    float4 v = *(const float4*)(src + i);
    v.x = rnd_tf32(v.x); v.y = rnd_tf32(v.y);
    v.z = rnd_tf32(v.z); v.w = rnd_tf32(v.w);
    *(float4*)(dst + i) = v;
}

// ---------------- bias table: bucket(distance) -> rel_emb lookup ------------
__global__ void bias_table_kernel(const float* __restrict__ rel_emb) {
    int i = blockIdx.x * blockDim.x + threadIdx.x;   // over H*S
    if (i >= HH * SS) return;
    int h = i / SS;
    int d = i % SS;
    int bucket;
    if (d < 16) {
        bucket = d;
    } else {
        float v = logf((float)d * (1.0f / 16.0f)) / 2.0794415416798357f * 16.0f;
        bucket = 16 + (int)v;
        if (bucket > 31) bucket = 31;
    }
    g_bias[h * SS + d] = rel_emb[bucket * HH + h];
}

// ---------------- RoPE cos/sin table (fp64 once, tiny) ----------------------
__global__ void rope_table_kernel() {
    int i = blockIdx.x * blockDim.x + threadIdx.x;   // SS*32
    if (i >= SS * 32) return;
    int s = i >> 5;
    int j = i & 31;
    double inv = pow(10000.0, -(double)j / 32.0);
    double a = (double)s * inv;
    g_cos[i] = (float)cos(a);
    g_sin[i] = (float)sin(a);
}

// ================= tf32 tensor-core GEMM core (3-stage pipeline) ============
#define GBM 128
#define GBN 128
#define GBK 32
#define LDA 36
#define LDBS 136
#define A_TILE (GBM*LDA)   // 4608 floats
#define B_TILE (GBK*LDBS)  // 4352 floats
#define GSTAGE (A_TILE + B_TILE)
#define GEMM_SMEM (GSTAGE * 3 * 4)   // 107520 bytes

__device__ __forceinline__ void gemm_load_stage(
    const float* __restrict__ A, const float* __restrict__ W,
    float* As, float* Bs, int m0, int n0, int k0, int tid)
{
    uint32_t aB = (uint32_t)__cvta_generic_to_shared(As);
    uint32_t bB = (uint32_t)__cvta_generic_to_shared(Bs);
#pragma unroll
    for (int i = 0; i < 4; i++) {
        int s = tid * 4 + i;
        int row = s >> 3, cs = s & 7;
        cpasync16(aB + (row * LDA + cs * 4) * 4,
                  A + (size_t)(m0 + row) * DD + k0 + cs * 4);
    }
#pragma unroll
    for (int i = 0; i < 4; i++) {
        int s = tid * 4 + i;
        int row = s >> 5, cs = s & 31;
        cpasync16(bB + (row * LDBS + cs * 4) * 4,
                  W + (size_t)(k0 + row) * DD + n0 + cs * 4);
    }
}

// inputs pre-rounded to tf32 -> fragments are raw bit loads.
__device__ __forceinline__ void gemm_body(
    const float* __restrict__ A, const float* __restrict__ W,
    float* __restrict__ C, int headLayout, float* sm, int m0, int n0)
{
    const int tid  = threadIdx.x;
    const int lane = tid & 31;
    const int wid  = tid >> 5;
    const int gid  = lane >> 2;
    const int tig  = lane & 3;
    const int wm   = (wid >> 2) * 64;
    const int wn   = (wid & 3) * 32;

    float c[4][4][4];
#pragma unroll
    for (int mt = 0; mt < 4; mt++)
#pragma unroll
        for (int nt = 0; nt < 4; nt++)
#pragma unroll
            for (int i = 0; i < 4; i++) c[mt][nt][i] = 0.0f;

    gemm_load_stage(A, W, sm, sm + A_TILE, m0, n0, 0, tid);
    asm volatile("cp.async.commit_group;");
    gemm_load_stage(A, W, sm + GSTAGE, sm + GSTAGE + A_TILE, m0, n0, GBK, tid);
    asm volatile("cp.async.commit_group;");

    const int NC = DD / GBK;   // 32
#pragma unroll 1
    for (int ch = 0; ch < NC; ch++) {
        if (ch + 1 < NC) asm volatile("cp.async.wait_group 1;");
        else             asm volatile("cp.async.wait_group 0;");
        __syncthreads();

        if (ch + 2 < NC) {
            float* dst = sm + ((ch + 2) % 3) * GSTAGE;
            gemm_load_stage(A, W, dst, dst + A_TILE, m0, n0, (ch + 2) * GBK, tid);
            asm volatile("cp.async.commit_group;");
        }

        const uint32_t* Asb = (const uint32_t*)(sm + (ch % 3) * GSTAGE);
        const uint32_t* Bsb = Asb + A_TILE;

#pragma unroll
        for (int ks = 0; ks < 4; ks++) {
            const int kb = ks * 8;
            uint32_t a[4][4], b[4][2];
#pragma unroll
            for (int mt = 0; mt < 4; mt++) {
                const uint32_t* ap = Asb + (wm + mt * 16 + gid) * LDA + kb + tig;
                a[mt][0] = ap[0];
                a[mt][1] = ap[8 * LDA];
                a[mt][2] = ap[4];
                a[mt][3] = ap[8 * LDA + 4];
            }
#pragma unroll
            for (int nt = 0; nt < 4; nt++) {
                const uint32_t* bp = Bsb + (kb + tig) * LDBS + wn + nt * 8 + gid;
                b[nt][0] = bp[0];
                b[nt][1] = bp[4 * LDBS];
            }
#pragma unroll
            for (int mt = 0; mt < 4; mt++)
#pragma unroll
                for (int nt = 0; nt < 4; nt++)
                    mma_tf32(c[mt][nt], a[mt], b[nt]);
        }
    }

#pragma unroll
    for (int mt = 0; mt < 4; mt++) {
#pragma unroll
        for (int nt = 0; nt < 4; nt++) {
            int row = m0 + wm + mt * 16 + gid;
            int col = n0 + wn + nt * 8 + 2 * tig;
            float2 v0 = make_float2(c[mt][nt][0], c[mt][nt][1]);
            float2 v1 = make_float2(c[mt][nt][2], c[mt][nt][3]);
            if (!headLayout) {
                *(float2*)&C[(size_t)row * DD + col] = v0;
                *(float2*)&C[(size_t)(row + 8) * DD + col] = v1;
            } else {
                int h = col >> 6, hd = col & 63;
                int b0i = row >> 11, s0 = row & 2047;
                int r1 = row + 8;
                int b1i = r1 >> 11, s1 = r1 & 2047;
                *(float2*)&C[(((size_t)(b0i * HH + h)) * SS + s0) * HD + hd] = v0;
                *(float2*)&C[(((size_t)(b1i * HH + h)) * SS + s1) * HD + hd] = v1;
            }
        }
    }
}

// fused QKV projection: one launch, N = 3072; weight + dest chosen per n-block
__global__ __launch_bounds__(256) void gemm_qkv() {
    extern __shared__ float sm[];
    const int n0g = blockIdx.x * GBN;
    const int z   = n0g >> 10;
    const int n0  = n0g & 1023;
    const float* W = g_Wc + (size_t)z * DD * DD;
    float* C = (z == 0) ? g_Q : (z == 1) ? g_K : g_V;
    gemm_body(g_xc, W, C, 1, sm, blockIdx.y * GBM, n0);
}

// output projection
__global__ __launch_bounds__(256) void gemm_out(float* __restrict__ out) {
    extern __shared__ float sm[];
    gemm_body(g_ctx, g_Wc + (size_t)3 * DD * DD, out, 0, sm,
              blockIdx.y * GBM, blockIdx.x * GBN);
}

// ---------------- RoPE in-place on Q,K + tf32 rounding of Q,K,V -------------
__global__ void rope_kernel() {
    int gid = blockIdx.x * blockDim.x + threadIdx.x;
    int j   = gid & 31;
    int row = gid >> 5;
    if (row >= BB * HH * SS) return;
    int s = row & (SS - 1);

    float c  = g_cos[s * 32 + j];
    float sn = g_sin[s * 32 + j];

    size_t base = (size_t)row * HD;
    float q0 = g_Q[base + j], q1 = g_Q[base + j + 32];
    g_Q[base + j]      = rnd_tf32(q0 * c - q1 * sn);
    g_Q[base + j + 32] = rnd_tf32(q1 * c + q0 * sn);
    float k0 = g_K[base + j], k1 = g_K[base + j + 32];
    g_K[base + j]      = rnd_tf32(k0 * c - k1 * sn);
    g_K[base + j + 32] = rnd_tf32(k1 * c + k0 * sn);
    g_V[base + j]      = rnd_tf32(g_V[base + j]);
    g_V[base + j + 32] = rnd_tf32(g_V[base + j + 32]);
}

// ============== tensor-core causal flash attention ==========================
#define LDS2 68
#define ATT_K_OFF 0
#define ATT_V_OFF (2*64*LDS2)
#define ATT_P_OFF (4*64*LDS2)
#define ATT_B_OFF (ATT_P_OFF + 128*LDS2)
#define ATT_SMEM ((ATT_B_OFF + 2*192) * 4)   // ~106 KB

__global__ __launch_bounds__(256) void attn_tc() {
    extern __shared__ float sm[];
    float* Ks = sm + ATT_K_OFF;
    float* Vs = sm + ATT_V_OFF;
    float* Ps = sm + ATT_P_OFF;
    float* Bw = sm + ATT_B_OFF;

    const int tid  = threadIdx.x;
    const int lane = tid & 31;
    const int w    = tid >> 5;
    const int gid  = lane >> 2;
    const int tig  = lane & 3;

    const int qt = (gridDim.x - 1) - blockIdx.x;   // long blocks first
    const int h  = blockIdx.y;
    const int b  = blockIdx.z;
    const int q0 = qt * 128;
    const int ktmax = 2 * qt + 1;

    const float* Qg = g_Q + (size_t)(b * HH + h) * SS * HD;
    const float* Kg = g_K + (size_t)(b * HH + h) * SS * HD;
    const float* Vg = g_V + (size_t)(b * HH + h) * SS * HD;
    const float* biasH = g_bias + h * SS;

    const uint32_t smBase = (uint32_t)__cvta_generic_to_shared(sm);

    auto prefetch = [&](int kt) {
        const int buf = kt & 1;
        const float* KgT = Kg + (size_t)kt * 64 * HD;
        const float* VgT = Vg + (size_t)kt * 64 * HD;
        uint32_t ka = smBase + (uint32_t)(ATT_K_OFF + buf * 64 * LDS2) * 4;
        uint32_t va = smBase + (uint32_t)(ATT_V_OFF + buf * 64 * LDS2) * 4;
#pragma unroll
        for (int i = 0; i < 4; i++) {
            int s = tid + i * 256;
            int r = s >> 4, c = (s & 15) * 4;
            cpasync16(ka + (r * LDS2 + c) * 4, KgT + r * HD + c);
            cpasync16(va + (r * LDS2 + c) * 4, VgT + r * HD + c);
        }
        int dlo = q0 - kt * 64 - 63;
        if (tid < 192) {
            int d = dlo + tid;
            int ok = (d >= 0 && d < SS) ? 4 : 0;
            int dc = d < 0 ? 0 : (d >= SS ? SS - 1 : d);
            uint32_t dst = smBase + (uint32_t)(ATT_B_OFF + buf * 192 + tid) * 4;
            asm volatile("cp.async.ca.shared.global [%0], [%1], 4, %2;"
                         :: "r"(dst), "l"(biasH + dc), "r"(ok));
        }
    };

    prefetch(0);
    asm volatile("cp.async.commit_group;");

#pragma unroll
    for (int i = 0; i < 8; i++) {
        int s = tid + i * 256;
        int r = s >> 4, c = (s & 15) * 4;
        *(float4*)&Ps[r * LDS2 + c] = *(const float4*)&Qg[(size_t)(q0 + r) * HD + c];
    }
    __syncthreads();

    uint32_t qa[8][4];
#pragma unroll
    for (int kc = 0; kc < 8; kc++) {
        const uint32_t* qp = (const uint32_t*)(Ps + (16 * w + gid) * LDS2 + kc * 8 + tig);
        qa[kc][0] = qp[0];
        qa[kc][1] = qp[8 * LDS2];
        qa[kc][2] = qp[4];
        qa[kc][3] = qp[8 * LDS2 + 4];
    }

    float o[8][4];
#pragma unroll
    for (int nt = 0; nt < 8; nt++)
#pragma unroll
        for (int i = 0; i < 4; i++) o[nt][i] = 0.0f;
    float m0 = -1e30f, m1 = -1e30f, l0 = 0.0f, l1 = 0.0f;

    const int qr0 = q0 + 16 * w + gid;
    float* pr0 = Ps + (16 * w + gid) * LDS2;
    float* pr1 = pr0 + 8 * LDS2;

    for (int kt = 0; kt <= ktmax; kt++) {
        if (kt < ktmax) {
            prefetch(kt + 1);
            asm volatile("cp.async.commit_group;");
            asm volatile("cp.async.wait_group 1;");
        } else {
            asm volatile("cp.async.wait_group 0;");
        }
        __syncthreads();

        const int k0 = kt * 64;
        const bool active = (k0 <= q0 + 16 * w + 15);
        if (active) {
            const uint32_t* Kb = (const uint32_t*)(Ks + (kt & 1) * 64 * LDS2);
            const uint32_t* Vb = (const uint32_t*)(Vs + (kt & 1) * 64 * LDS2);
            const float* bw = Bw + (kt & 1) * 192;
            const int dlo = q0 - k0 - 63;

            float s_[8][4];
#pragma unroll
            for (int nt = 0; nt < 8; nt++)
#pragma unroll
                for (int i = 0; i < 4; i++) s_[nt][i] = 0.0f;

#pragma unroll
            for (int kc = 0; kc < 8; kc++) {
#pragma unroll
                for (int nt = 0; nt < 8; nt++) {
                    const uint32_t* kp = Kb + (nt * 8 + gid) * LDS2 + kc * 8 + tig;
                    uint32_t bf[2] = { kp[0], kp[4] };
                    mma_tf32(s_[nt], qa[kc], bf);
                }
            }

            const int r0 = qr0, r1 = qr0 + 8;
            const bool needMask = (k0 + 63 > r0);
            float mx0 = m0, mx1 = m1;
#pragma unroll
            for (int nt = 0; nt < 8; nt++) {
                int c0 = k0 + nt * 8 + 2 * tig;
                s_[nt][0] = s_[nt][0] * 0.125f + bw[r0 - c0 - dlo];
                s_[nt][1] = s_[nt][1] * 0.125f + bw[r0 - c0 - 1 - dlo];
                s_[nt][2] = s_[nt][2] * 0.125f + bw[r1 - c0 - dlo];
                s_[nt][3] = s_[nt][3] * 0.125f + bw[r1 - c0 - 1 - dlo];
                if (needMask) {
                    if (c0     > r0) s_[nt][0] = -1e9f;
                    if (c0 + 1 > r0) s_[nt][1] = -1e9f;
                    if (c0     > r1) s_[nt][2] = -1e9f;
                    if (c0 + 1 > r1) s_[nt][3] = -1e9f;
                }
                mx0 = fmaxf(mx0, fmaxf(s_[nt][0], s_[nt][1]));
                mx1 = fmaxf(mx1, fmaxf(s_[nt][2], s_[nt][3]));
            }
            mx0 = fmaxf(mx0, __shfl_xor_sync(0xffffffffu, mx0, 1));
            mx0 = fmaxf(mx0, __shfl_xor_sync(0xffffffffu, mx0, 2));
            mx1 = fmaxf(mx1, __shfl_xor_sync(0xffffffffu, mx1, 1));
            mx1 = fmaxf(mx1, __shfl_xor_sync(0xffffffffu, mx1, 2));

            float corr0 = __expf(m0 - mx0);
            float corr1 = __expf(m1 - mx1);
            m0 = mx0; m1 = mx1;

            float ls0 = 0.0f, ls1 = 0.0f;
#pragma unroll
            for (int nt = 0; nt < 8; nt++) {
                int c = nt * 8 + 2 * tig;
                float p00 = __expf(s_[nt][0] - mx0);
                float p01 = __expf(s_[nt][1] - mx0);
                float p10 = __expf(s_[nt][2] - mx1);
                float p11 = __expf(s_[nt][3] - mx1);
                ls0 += p00 + p01;
                ls1 += p10 + p11;
                *(float2*)&pr0[c] = make_float2(p00, p01);
                *(float2*)&pr1[c] = make_float2(p10, p11);
                o[nt][0] *= corr0; o[nt][1] *= corr0;
                o[nt][2] *= corr1; o[nt][3] *= corr1;
            }
            ls0 += __shfl_xor_sync(0xffffffffu, ls0, 1);
            ls0 += __shfl_xor_sync(0xffffffffu, ls0, 2);
            ls1 += __shfl_xor_sync(0xffffffffu, ls1, 1);
            ls1 += __shfl_xor_sync(0xffffffffu, ls1, 2);
            l0 = l0 * corr0 + ls0;
            l1 = l1 * corr1 + ls1;
            __syncwarp();

#pragma unroll
            for (int kc = 0; kc < 8; kc++) {
                const float* pp = Ps + (16 * w + gid) * LDS2 + kc * 8 + tig;
                uint32_t pa[4] = { f2tf32(pp[0]), f2tf32(pp[8 * LDS2]),
                                   f2tf32(pp[4]), f2tf32(pp[8 * LDS2 + 4]) };
#pragma unroll
                for (int nt = 0; nt < 8; nt++) {
                    const uint32_t* vp = Vb + (kc * 8 + tig) * LDS2 + nt * 8 + gid;
                    uint32_t bf[2] = { vp[0], vp[4 * LDS2] };
                    mma_tf32(o[nt], pa, bf);
                }
            }
            __syncwarp();
        }
        __syncthreads();
    }

    const float inv0 = 1.0f / l0;
    const float inv1 = 1.0f / l1;
    const int hbase = h * HD;
#pragma unroll
    for (int nt = 0; nt < 8; nt++) {
        int c = hbase + nt * 8 + 2 * tig;
        *(float2*)&g_ctx[((size_t)b * SS + qr0) * DD + c] =
            make_float2(rnd_tf32(o[nt][0] * inv0), rnd_tf32(o[nt][1] * inv0));
        *(float2*)&g_ctx[((size_t)b * SS + qr0 + 8) * DD + c] =
            make_float2(rnd_tf32(o[nt][2] * inv1), rnd_tf32(o[nt][3] * inv1));
    }
}

// ---------------- launcher --------------------------------------------------
extern "C" void kernel_launch(void* const* d_in, const int* in_sizes, int n_in,
                              void* d_out, int out_size)
{
    const float* x   = (const float*)d_in[0];
    const float* Wq  = (const float*)d_in[1];
    const float* Wk  = (const float*)d_in[2];
    const float* Wv  = (const float*)d_in[3];
    const float* Wo  = (const float*)d_in[4];
    const float* rel = (const float*)d_in[5];
    float* out = (float*)d_out;

    float *xc, *Wc;
    cudaGetSymbolAddress((void**)&xc, g_xc);
    cudaGetSymbolAddress((void**)&Wc, g_Wc);

    cudaFuncSetAttribute(gemm_qkv, cudaFuncAttributeMaxDynamicSharedMemorySize, GEMM_SMEM);
    cudaFuncSetAttribute(gemm_out, cudaFuncAttributeMaxDynamicSharedMemorySize, GEMM_SMEM);
    cudaFuncSetAttribute(attn_tc, cudaFuncAttributeMaxDynamicSharedMemorySize, ATT_SMEM);

    // 1) setup tables + tf32 pre-rounding of inputs
    bias_table_kernel<<<(HH * SS + 255) / 256, 256>>>(rel);
    rope_table_kernel<<<(SS * 32 + 255) / 256, 256>>>();
    round_tf32_kernel<<<(MROWS * DD / 4 + 255) / 256, 256>>>(x, xc, MROWS * DD);
    round_tf32_kernel<<<(DD * DD / 4 + 255) / 256, 256>>>(Wq, Wc + 0 * DD * DD, DD * DD);
    round_tf32_kernel<<<(DD * DD / 4 + 255) / 256, 256>>>(Wk, Wc + 1 * DD * DD, DD * DD);
    round_tf32_kernel<<<(DD * DD / 4 + 255) / 256, 256>>>(Wv, Wc + 2 * DD * DD, DD * DD);
    round_tf32_kernel<<<(DD * DD / 4 + 255) / 256, 256>>>(Wo, Wc + 3 * DD * DD, DD * DD);

    // 2) fused QKV projections (N = 3072, scatter to [B,H,S,HD])
    gemm_qkv<<<dim3(3 * DD / GBN, MROWS / GBM), 256, GEMM_SMEM>>>();

    // 3) RoPE on Q,K (+ tf32 rounding of Q,K,V)
    rope_kernel<<<(BB * HH * SS * 32) / 256, 256>>>();

    // 4) tensor-core causal attention with bias
    attn_tc<<<dim3(SS / 128, HH, BB), 256, ATT_SMEM>>>();

    // 5) output projection
    gemm_out<<<dim3(DD / GBN, MROWS / GBM), 256, GEMM_SMEM>>>(out);
}

// round 8
// speedup vs baseline: 5.2880x; 1.5341x over previous
#include <cuda_runtime.h>
#include <cuda_fp16.h>
#include <math.h>
#include <stdint.h>

#define BB 2
#define SS 2048
#define DD 1024
#define HH 16
#define HD 64
#define MROWS (BB*SS)   // 4096

// ---------------- scratch (device globals; no allocations allowed) ----------
__device__ float  g_Q[BB*HH*SS*HD];
__device__ float  g_K[BB*HH*SS*HD];
__device__ float  g_V[BB*HH*SS*HD];
__device__ __half g_ctxh[MROWS*DD];
__device__ float  g_bias[HH*SS];     // bias[h][distance], distance = q - k >= 0
__device__ float  g_cos[SS*32];
__device__ float  g_sin[SS*32];
__device__ __half g_xh[MROWS*DD];    // fp16 x
__device__ __half g_Wh[4*DD*DD];     // fp16 TRANSPOSED Wq,Wk,Wv,Wo ([N][K])

// ---------------- common PTX helpers ----------------------------------------
__device__ __forceinline__ void cpasync16(uint32_t s, const void* g) {
    asm volatile("cp.async.cg.shared.global [%0], [%1], 16;" :: "r"(s), "l"(g));
}
__device__ __forceinline__ uint32_t f2tf32(float x) {
    uint32_t r;
    asm("cvt.rna.tf32.f32 %0, %1;" : "=r"(r) : "f"(x));
    return r;
}
__device__ __forceinline__ float rnd_tf32(float x) {
    return __uint_as_float(f2tf32(x));
}
__device__ __forceinline__ void mma_tf32(float* c, const uint32_t* a, const uint32_t* b) {
    asm volatile(
        "mma.sync.aligned.m16n8k8.row.col.f32.tf32.tf32.f32 "
        "{%0,%1,%2,%3},{%4,%5,%6,%7},{%8,%9},{%0,%1,%2,%3};"
        : "+f"(c[0]), "+f"(c[1]), "+f"(c[2]), "+f"(c[3])
        : "r"(a[0]), "r"(a[1]), "r"(a[2]), "r"(a[3]), "r"(b[0]), "r"(b[1]));
}
__device__ __forceinline__ void mma_f16(float* c, const uint32_t* a, const uint32_t* b) {
    asm volatile(
        "mma.sync.aligned.m16n8k16.row.col.f32.f16.f16.f32 "
        "{%0,%1,%2,%3},{%4,%5,%6,%7},{%8,%9},{%0,%1,%2,%3};"
        : "+f"(c[0]), "+f"(c[1]), "+f"(c[2]), "+f"(c[3])
        : "r"(a[0]), "r"(a[1]), "r"(a[2]), "r"(a[3]), "r"(b[0]), "r"(b[1]));
}

// ---------------- x -> fp16 -------------------------------------------------
__global__ void to_half_kernel(const float* __restrict__ src,
                               __half* __restrict__ dst, int n) {
    int i = (blockIdx.x * blockDim.x + threadIdx.x) * 4;
    if (i >= n) return;
    float4 v = *(const float4*)(src + i);
    *(__half2*)(dst + i)     = __floats2half2_rn(v.x, v.y);
    *(__half2*)(dst + i + 2) = __floats2half2_rn(v.z, v.w);
}

// ---------------- W transpose + fp16: g_Wh[z][n][k] = (half)W[k][n] ---------
__global__ void transpose_half_kernel(const float* __restrict__ W0,
                                      const float* __restrict__ W1,
                                      const float* __restrict__ W2,
                                      const float* __restrict__ W3) {
    __shared__ float t[32][33];
    const float* W = (blockIdx.z == 0) ? W0 : (blockIdx.z == 1) ? W1
                   : (blockIdx.z == 2) ? W2 : W3;
    __half* Wt = g_Wh + (size_t)blockIdx.z * DD * DD;
    int bn = blockIdx.x * 32;   // n tile
    int bk = blockIdx.y * 32;   // k tile
    int tx = threadIdx.x, ty = threadIdx.y;
#pragma unroll
    for (int i = 0; i < 4; i++)
        t[ty + 8 * i][tx] = W[(size_t)(bk + ty + 8 * i) * DD + bn + tx];
    __syncthreads();
#pragma unroll
    for (int i = 0; i < 4; i++)
        Wt[(size_t)(bn + ty + 8 * i) * DD + bk + tx] = __float2half(t[tx][ty + 8 * i]);
}

// ---------------- bias table: bucket(distance) -> rel_emb lookup ------------
__global__ void bias_table_kernel(const float* __restrict__ rel_emb) {
    int i = blockIdx.x * blockDim.x + threadIdx.x;   // over H*S
    if (i >= HH * SS) return;
    int h = i / SS;
    int d = i % SS;
    int bucket;
    if (d < 16) {
        bucket = d;
    } else {
        float v = logf((float)d * (1.0f / 16.0f)) / 2.0794415416798357f * 16.0f;
        bucket = 16 + (int)v;
        if (bucket > 31) bucket = 31;
    }
    g_bias[h * SS + d] = rel_emb[bucket * HH + h];
}

// ---------------- RoPE cos/sin table (fp64 once, tiny) ----------------------
__global__ void rope_table_kernel() {
    int i = blockIdx.x * blockDim.x + threadIdx.x;   // SS*32
    if (i >= SS * 32) return;
    int s = i >> 5;
    int j = i & 31;
    double inv = pow(10000.0, -(double)j / 32.0);
    double a = (double)s * inv;
    g_cos[i] = (float)cos(a);
    g_sin[i] = (float)sin(a);
}

// ================= fp16 tensor-core GEMM (m16n8k16) =========================
// C[4096,1024] = A[4096,1024] @ Wt^T, A row-major half, Wt [N][K] half.
// Block tile 128x128, k-chunk 64, 256 threads (8 warps 2x4), warp tile 64x32.
#define LDAH 72                    // halves per row (=36 words; 4g+t banks, conflict-free)
#define H_TILE (128*LDAH)          // halves per tile (A or B)
#define HSTAGE (2*H_TILE)          // halves per stage (A+B)
#define GEMM_SMEM (HSTAGE * 2 * 2) // bytes: 2 stages * 2B = 73728

__device__ __forceinline__ void gemm_load_stage_h(
    const __half* __restrict__ A, const __half* __restrict__ Bt,
    uint32_t aB, uint32_t bB, int m0, int n0, int k0, int tid)
{
#pragma unroll
    for (int i = 0; i < 4; i++) {
        int s = tid + i * 256;          // 1024 segs: 128 rows x 8 (16B = 8 halves)
        int r = s >> 3, cs = s & 7;
        cpasync16(aB + (uint32_t)(r * (LDAH * 2) + cs * 16),
                  A + (size_t)(m0 + r) * DD + k0 + cs * 8);
        cpasync16(bB + (uint32_t)(r * (LDAH * 2) + cs * 16),
                  Bt + (size_t)(n0 + r) * DD + k0 + cs * 8);
    }
}

__device__ __forceinline__ void gemm_body_h(
    const __half* __restrict__ A, const __half* __restrict__ Bt,
    float* __restrict__ Cf, int headLayout, int m0, int n0)
{
    extern __shared__ __half smh[];
    uint32_t smBase = (uint32_t)__cvta_generic_to_shared(smh);
    const int tid  = threadIdx.x;
    const int lane = tid & 31;
    const int wid  = tid >> 5;
    const int gid  = lane >> 2;
    const int tig  = lane & 3;
    const int wm   = (wid >> 2) * 64;
    const int wn   = (wid & 3) * 32;

    float c[4][4][4];
#pragma unroll
    for (int mt = 0; mt < 4; mt++)
#pragma unroll
        for (int nt = 0; nt < 4; nt++)
#pragma unroll
            for (int i = 0; i < 4; i++) c[mt][nt][i] = 0.0f;

    const uint32_t stB = HSTAGE * 2;   // stage stride in bytes
    gemm_load_stage_h(A, Bt, smBase, smBase + H_TILE * 2, m0, n0, 0, tid);
    asm volatile("cp.async.commit_group;");

    const int NC = DD / 64;   // 16
#pragma unroll 1
    for (int ch = 0; ch < NC; ch++) {
        if (ch + 1 < NC) {
            uint32_t db = smBase + ((ch + 1) & 1) * stB;
            gemm_load_stage_h(A, Bt, db, db + H_TILE * 2, m0, n0, (ch + 1) * 64, tid);
            asm volatile("cp.async.commit_group;");
            asm volatile("cp.async.wait_group 1;");
        } else {
            asm volatile("cp.async.wait_group 0;");
        }
        __syncthreads();

        const uint32_t* Asb = (const uint32_t*)(smh + (ch & 1) * HSTAGE);
        const uint32_t* Bsb = Asb + H_TILE / 2;

#pragma unroll
        for (int ks = 0; ks < 4; ks++) {
            const int kbw = ks * 8;    // word offset (16 halves per k-step)
            uint32_t a[4][4], b[4][2];
#pragma unroll
            for (int mt = 0; mt < 4; mt++) {
                const uint32_t* ap = Asb + (wm + mt * 16 + gid) * (LDAH / 2) + kbw + tig;
                a[mt][0] = ap[0];
                a[mt][1] = ap[8 * (LDAH / 2)];
                a[mt][2] = ap[4];
                a[mt][3] = ap[8 * (LDAH / 2) + 4];
            }
#pragma unroll
            for (int nt = 0; nt < 4; nt++) {
                const uint32_t* bp = Bsb + (wn + nt * 8 + gid) * (LDAH / 2) + kbw + tig;
                b[nt][0] = bp[0];
                b[nt][1] = bp[4];
            }
#pragma unroll
            for (int mt = 0; mt < 4; mt++)
#pragma unroll
                for (int nt = 0; nt < 4; nt++)
                    mma_f16(c[mt][nt], a[mt], b[nt]);
        }
        __syncthreads();
    }

#pragma unroll
    for (int mt = 0; mt < 4; mt++) {
#pragma unroll
        for (int nt = 0; nt < 4; nt++) {
            int row = m0 + wm + mt * 16 + gid;
            int col = n0 + wn + nt * 8 + 2 * tig;
            float2 v0 = make_float2(c[mt][nt][0], c[mt][nt][1]);
            float2 v1 = make_float2(c[mt][nt][2], c[mt][nt][3]);
            if (!headLayout) {
                *(float2*)&Cf[(size_t)row * DD + col] = v0;
                *(float2*)&Cf[(size_t)(row + 8) * DD + col] = v1;
            } else {
                int h = col >> 6, hd = col & 63;
                int b0i = row >> 11, s0 = row & 2047;
                int r1 = row + 8;
                int b1i = r1 >> 11, s1 = r1 & 2047;
                *(float2*)&Cf[(((size_t)(b0i * HH + h)) * SS + s0) * HD + hd] = v0;
                *(float2*)&Cf[(((size_t)(b1i * HH + h)) * SS + s1) * HD + hd] = v1;
            }
        }
    }
}

// fused QKV projection: N = 3072; scatter to [B,H,S,HD] fp32
__global__ __launch_bounds__(256) void gemm_qkv() {
    const int n0g = blockIdx.x * 128;
    const int z   = n0g >> 10;
    const int n0  = n0g & 1023;
    const __half* Bt = g_Wh + (size_t)z * DD * DD;
    float* C = (z == 0) ? g_Q : (z == 1) ? g_K : g_V;
    gemm_body_h(g_xh, Bt, C, 1, blockIdx.y * 128, n0);
}

// output projection (ctx half -> out fp32)
__global__ __launch_bounds__(256) void gemm_out(float* __restrict__ out) {
    gemm_body_h(g_ctxh, g_Wh + (size_t)3 * DD * DD, out, 0,
                blockIdx.y * 128, blockIdx.x * 128);
}

// ---------------- RoPE in-place on Q,K + tf32 rounding of Q,K,V -------------
__global__ void rope_kernel() {
    int gid = blockIdx.x * blockDim.x + threadIdx.x;
    int j   = gid & 31;
    int row = gid >> 5;
    if (row >= BB * HH * SS) return;
    int s = row & (SS - 1);

    float c  = g_cos[s * 32 + j];
    float sn = g_sin[s * 32 + j];

    size_t base = (size_t)row * HD;
    float q0 = g_Q[base + j], q1 = g_Q[base + j + 32];
    g_Q[base + j]      = rnd_tf32(q0 * c - q1 * sn);
    g_Q[base + j + 32] = rnd_tf32(q1 * c + q0 * sn);
    float k0 = g_K[base + j], k1 = g_K[base + j + 32];
    g_K[base + j]      = rnd_tf32(k0 * c - k1 * sn);
    g_K[base + j + 32] = rnd_tf32(k1 * c + k0 * sn);
    g_V[base + j]      = rnd_tf32(g_V[base + j]);
    g_V[base + j + 32] = rnd_tf32(g_V[base + j + 32]);
}

// ============== tensor-core causal flash attention (tf32, proven) ===========
#define LDS2 68
#define ATT_K_OFF 0
#define ATT_V_OFF (2*64*LDS2)
#define ATT_P_OFF (4*64*LDS2)
#define ATT_B_OFF (ATT_P_OFF + 128*LDS2)
#define ATT_SMEM ((ATT_B_OFF + 2*192) * 4)   // ~106 KB

__global__ __launch_bounds__(256) void attn_tc() {
    extern __shared__ float sm[];
    float* Ks = sm + ATT_K_OFF;
    float* Vs = sm + ATT_V_OFF;
    float* Ps = sm + ATT_P_OFF;
    float* Bw = sm + ATT_B_OFF;

    const int tid  = threadIdx.x;
    const int lane = tid & 31;
    const int w    = tid >> 5;
    const int gid  = lane >> 2;
    const int tig  = lane & 3;

    const int qt = (gridDim.x - 1) - blockIdx.x;   // long blocks first
    const int h  = blockIdx.y;
    const int b  = blockIdx.z;
    const int q0 = qt * 128;
    const int ktmax = 2 * qt + 1;

    const float* Qg = g_Q + (size_t)(b * HH + h) * SS * HD;
    const float* Kg = g_K + (size_t)(b * HH + h) * SS * HD;
    const float* Vg = g_V + (size_t)(b * HH + h) * SS * HD;
    const float* biasH = g_bias + h * SS;

    const uint32_t smBase = (uint32_t)__cvta_generic_to_shared(sm);

    auto prefetch = [&](int kt) {
        const int buf = kt & 1;
        const float* KgT = Kg + (size_t)kt * 64 * HD;
        const float* VgT = Vg + (size_t)kt * 64 * HD;
        uint32_t ka = smBase + (uint32_t)(ATT_K_OFF + buf * 64 * LDS2) * 4;
        uint32_t va = smBase + (uint32_t)(ATT_V_OFF + buf * 64 * LDS2) * 4;
#pragma unroll
        for (int i = 0; i < 4; i++) {
            int s = tid + i * 256;
            int r = s >> 4, c = (s & 15) * 4;
            cpasync16(ka + (r * LDS2 + c) * 4, KgT + r * HD + c);
            cpasync16(va + (r * LDS2 + c) * 4, VgT + r * HD + c);
        }
        int dlo = q0 - kt * 64 - 63;
        if (tid < 192) {
            int d = dlo + tid;
            int ok = (d >= 0 && d < SS) ? 4 : 0;
            int dc = d < 0 ? 0 : (d >= SS ? SS - 1 : d);
            uint32_t dst = smBase + (uint32_t)(ATT_B_OFF + buf * 192 + tid) * 4;
            asm volatile("cp.async.ca.shared.global [%0], [%1], 4, %2;"
                         :: "r"(dst), "l"(biasH + dc), "r"(ok));
        }
    };

    prefetch(0);
    asm volatile("cp.async.commit_group;");

#pragma unroll
    for (int i = 0; i < 8; i++) {
        int s = tid + i * 256;
        int r = s >> 4, c = (s & 15) * 4;
        *(float4*)&Ps[r * LDS2 + c] = *(const float4*)&Qg[(size_t)(q0 + r) * HD + c];
    }
    __syncthreads();

    uint32_t qa[8][4];
#pragma unroll
    for (int kc = 0; kc < 8; kc++) {
        const uint32_t* qp = (const uint32_t*)(Ps + (16 * w + gid) * LDS2 + kc * 8 + tig);
        qa[kc][0] = qp[0];
        qa[kc][1] = qp[8 * LDS2];
        qa[kc][2] = qp[4];
        qa[kc][3] = qp[8 * LDS2 + 4];
    }

    float o[8][4];
#pragma unroll
    for (int nt = 0; nt < 8; nt++)
#pragma unroll
        for (int i = 0; i < 4; i++) o[nt][i] = 0.0f;
    float m0 = -1e30f, m1 = -1e30f, l0 = 0.0f, l1 = 0.0f;

    const int qr0 = q0 + 16 * w + gid;
    float* pr0 = Ps + (16 * w + gid) * LDS2;
    float* pr1 = pr0 + 8 * LDS2;

    for (int kt = 0; kt <= ktmax; kt++) {
        if (kt < ktmax) {
            prefetch(kt + 1);
            asm volatile("cp.async.commit_group;");
            asm volatile("cp.async.wait_group 1;");
        } else {
            asm volatile("cp.async.wait_group 0;");
        }
        __syncthreads();

        const int k0 = kt * 64;
        const bool active = (k0 <= q0 + 16 * w + 15);
        if (active) {
            const uint32_t* Kb = (const uint32_t*)(Ks + (kt & 1) * 64 * LDS2);
            const uint32_t* Vb = (const uint32_t*)(Vs + (kt & 1) * 64 * LDS2);
            const float* bw = Bw + (kt & 1) * 192;
            const int dlo = q0 - k0 - 63;

            float s_[8][4];
#pragma unroll
            for (int nt = 0; nt < 8; nt++)
#pragma unroll
                for (int i = 0; i < 4; i++) s_[nt][i] = 0.0f;

#pragma unroll
            for (int kc = 0; kc < 8; kc++) {
#pragma unroll
                for (int nt = 0; nt < 8; nt++) {
                    const uint32_t* kp = Kb + (nt * 8 + gid) * LDS2 + kc * 8 + tig;
                    uint32_t bf[2] = { kp[0], kp[4] };
                    mma_tf32(s_[nt], qa[kc], bf);
                }
            }

            const int r0 = qr0, r1 = qr0 + 8;
            const bool needMask = (k0 + 63 > r0);
            float mx0 = m0, mx1 = m1;
#pragma unroll
            for (int nt = 0; nt < 8; nt++) {
                int c0 = k0 + nt * 8 + 2 * tig;
                s_[nt][0] = s_[nt][0] * 0.125f + bw[r0 - c0 - dlo];
                s_[nt][1] = s_[nt][1] * 0.125f + bw[r0 - c0 - 1 - dlo];
                s_[nt][2] = s_[nt][2] * 0.125f + bw[r1 - c0 - dlo];
                s_[nt][3] = s_[nt][3] * 0.125f + bw[r1 - c0 - 1 - dlo];
                if (needMask) {
                    if (c0     > r0) s_[nt][0] = -1e9f;
                    if (c0 + 1 > r0) s_[nt][1] = -1e9f;
                    if (c0     > r1) s_[nt][2] = -1e9f;
                    if (c0 + 1 > r1) s_[nt][3] = -1e9f;
                }
                mx0 = fmaxf(mx0, fmaxf(s_[nt][0], s_[nt][1]));
                mx1 = fmaxf(mx1, fmaxf(s_[nt][2], s_[nt][3]));
            }
            mx0 = fmaxf(mx0, __shfl_xor_sync(0xffffffffu, mx0, 1));
            mx0 = fmaxf(mx0, __shfl_xor_sync(0xffffffffu, mx0, 2));
            mx1 = fmaxf(mx1, __shfl_xor_sync(0xffffffffu, mx1, 1));
            mx1 = fmaxf(mx1, __shfl_xor_sync(0xffffffffu, mx1, 2));

            float corr0 = __expf(m0 - mx0);
            float corr1 = __expf(m1 - mx1);
            m0 = mx0; m1 = mx1;

            float ls0 = 0.0f, ls1 = 0.0f;
#pragma unroll
            for (int nt = 0; nt < 8; nt++) {
                int c = nt * 8 + 2 * tig;
                float p00 = __expf(s_[nt][0] - mx0);
                float p01 = __expf(s_[nt][1] - mx0);
                float p10 = __expf(s_[nt][2] - mx1);
                float p11 = __expf(s_[nt][3] - mx1);
                ls0 += p00 + p01;
                ls1 += p10 + p11;
                *(float2*)&pr0[c] = make_float2(p00, p01);
                *(float2*)&pr1[c] = make_float2(p10, p11);
                o[nt][0] *= corr0; o[nt][1] *= corr0;
                o[nt][2] *= corr1; o[nt][3] *= corr1;
            }
            ls0 += __shfl_xor_sync(0xffffffffu, ls0, 1);
            ls0 += __shfl_xor_sync(0xffffffffu, ls0, 2);
            ls1 += __shfl_xor_sync(0xffffffffu, ls1, 1);
            ls1 += __shfl_xor_sync(0xffffffffu, ls1, 2);
            l0 = l0 * corr0 + ls0;
            l1 = l1 * corr1 + ls1;
            __syncwarp();

#pragma unroll
            for (int kc = 0; kc < 8; kc++) {
                const float* pp = Ps + (16 * w + gid) * LDS2 + kc * 8 + tig;
                uint32_t pa[4] = { f2tf32(pp[0]), f2tf32(pp[8 * LDS2]),
                                   f2tf32(pp[4]), f2tf32(pp[8 * LDS2 + 4]) };
#pragma unroll
                for (int nt = 0; nt < 8; nt++) {
                    const uint32_t* vp = Vb + (kc * 8 + tig) * LDS2 + nt * 8 + gid;
                    uint32_t bf[2] = { vp[0], vp[4 * LDS2] };
                    mma_tf32(o[nt], pa, bf);
                }
            }
            __syncwarp();
        }
        __syncthreads();
    }

    // epilogue: ctx emitted as fp16 (feeds fp16 Wo GEMM)
    const float inv0 = 1.0f / l0;
    const float inv1 = 1.0f / l1;
    const int hbase = h * HD;
#pragma unroll
    for (int nt = 0; nt < 8; nt++) {
        int c = hbase + nt * 8 + 2 * tig;
        *(__half2*)&g_ctxh[((size_t)b * SS + qr0) * DD + c] =
            __floats2half2_rn(o[nt][0] * inv0, o[nt][1] * inv0);
        *(__half2*)&g_ctxh[((size_t)b * SS + qr0 + 8) * DD + c] =
            __floats2half2_rn(o[nt][2] * inv1, o[nt][3] * inv1);
    }
}

// ---------------- launcher --------------------------------------------------
extern "C" void kernel_launch(void* const* d_in, const int* in_sizes, int n_in,
                              void* d_out, int out_size)
{
    const float* x   = (const float*)d_in[0];
    const float* Wq  = (const float*)d_in[1];
    const float* Wk  = (const float*)d_in[2];
    const float* Wv  = (const float*)d_in[3];
    const float* Wo  = (const float*)d_in[4];
    const float* rel = (const float*)d_in[5];
    float* out = (float*)d_out;

    __half* xh;
    cudaGetSymbolAddress((void**)&xh, g_xh);

    cudaFuncSetAttribute(gemm_qkv, cudaFuncAttributeMaxDynamicSharedMemorySize, GEMM_SMEM);
    cudaFuncSetAttribute(gemm_out, cudaFuncAttributeMaxDynamicSharedMemorySize, GEMM_SMEM);
    cudaFuncSetAttribute(attn_tc, cudaFuncAttributeMaxDynamicSharedMemorySize, ATT_SMEM);

    // 1) setup tables + fp16 conversion of inputs
    bias_table_kernel<<<(HH * SS + 255) / 256, 256>>>(rel);
    rope_table_kernel<<<(SS * 32 + 255) / 256, 256>>>();
    to_half_kernel<<<(MROWS * DD / 4 + 255) / 256, 256>>>(x, xh, MROWS * DD);
    transpose_half_kernel<<<dim3(DD / 32, DD / 32, 4), dim3(32, 8)>>>(Wq, Wk, Wv, Wo);

    // 2) fused QKV projections, fp16 tensor cores (scatter to [B,H,S,HD] fp32)
    gemm_qkv<<<dim3(3 * DD / 128, MROWS / 128), 256, GEMM_SMEM>>>();

    // 3) RoPE on Q,K (+ tf32 rounding of Q,K,V for the attention mma path)
    rope_kernel<<<(BB * HH * SS * 32) / 256, 256>>>();

    // 4) tensor-core causal attention with bias (tf32)
    attn_tc<<<dim3(SS / 128, HH, BB), 256, ATT_SMEM>>>();

    // 5) output projection, fp16 tensor cores
    gemm_out<<<dim3(DD / 128, MROWS / 128), 256, GEMM_SMEM>>>(out);
}

// round 9
// speedup vs baseline: 7.3191x; 1.3841x over previous
#include <cuda_runtime.h>
#include <cuda_fp16.h>
#include <math.h>
#include <stdint.h>

#define BB 2
#define SS 2048
#define DD 1024
#define HH 16
#define HD 64
#define MROWS (BB*SS)   // 4096

// ---------------- scratch (device globals; no allocations allowed) ----------
__device__ float  g_Q[BB*HH*SS*HD];     // fp32 pre-rope QKV from GEMM
__device__ float  g_K[BB*HH*SS*HD];
__device__ float  g_V[BB*HH*SS*HD];
__device__ __half g_Qh[BB*HH*SS*HD];    // fp16 post-rope Q [b,h,s,hd]
__device__ __half g_Kh[BB*HH*SS*HD];    // fp16 post-rope K [b,h,s,hd]
__device__ __half g_Vth[BB*HH*HD*SS];   // fp16 V TRANSPOSED [b,h,hd,s]
__device__ __half g_ctxh[MROWS*DD];
__device__ float  g_bias[HH*SS];        // bias[h][distance], distance = q-k >= 0
__device__ float  g_cos[SS*32];
__device__ float  g_sin[SS*32];
__device__ __half g_xh[MROWS*DD];       // fp16 x
__device__ __half g_Wh[4*DD*DD];        // fp16 TRANSPOSED Wq,Wk,Wv,Wo ([N][K])

// ---------------- common PTX helpers ----------------------------------------
__device__ __forceinline__ void cpasync16(uint32_t s, const void* g) {
    asm volatile("cp.async.cg.shared.global [%0], [%1], 16;" :: "r"(s), "l"(g));
}
__device__ __forceinline__ void mma_f16(float* c, const uint32_t* a, const uint32_t* b) {
    asm volatile(
        "mma.sync.aligned.m16n8k16.row.col.f32.f16.f16.f32 "
        "{%0,%1,%2,%3},{%4,%5,%6,%7},{%8,%9},{%0,%1,%2,%3};"
        : "+f"(c[0]), "+f"(c[1]), "+f"(c[2]), "+f"(c[3])
        : "r"(a[0]), "r"(a[1]), "r"(a[2]), "r"(a[3]), "r"(b[0]), "r"(b[1]));
}

// ---------------- x -> fp16 -------------------------------------------------
__global__ void to_half_kernel(const float* __restrict__ src,
                               __half* __restrict__ dst, int n) {
    int i = (blockIdx.x * blockDim.x + threadIdx.x) * 4;
    if (i >= n) return;
    float4 v = *(const float4*)(src + i);
    *(__half2*)(dst + i)     = __floats2half2_rn(v.x, v.y);
    *(__half2*)(dst + i + 2) = __floats2half2_rn(v.z, v.w);
}

// ---------------- W transpose + fp16: g_Wh[z][n][k] = (half)W[k][n] ---------
__global__ void transpose_half_kernel(const float* __restrict__ W0,
                                      const float* __restrict__ W1,
                                      const float* __restrict__ W2,
                                      const float* __restrict__ W3) {
    __shared__ float t[32][33];
    const float* W = (blockIdx.z == 0) ? W0 : (blockIdx.z == 1) ? W1
                   : (blockIdx.z == 2) ? W2 : W3;
    __half* Wt = g_Wh + (size_t)blockIdx.z * DD * DD;
    int bn = blockIdx.x * 32;
    int bk = blockIdx.y * 32;
    int tx = threadIdx.x, ty = threadIdx.y;
#pragma unroll
    for (int i = 0; i < 4; i++)
        t[ty + 8 * i][tx] = W[(size_t)(bk + ty + 8 * i) * DD + bn + tx];
    __syncthreads();
#pragma unroll
    for (int i = 0; i < 4; i++)
        Wt[(size_t)(bn + ty + 8 * i) * DD + bk + tx] = __float2half(t[tx][ty + 8 * i]);
}

// ---------------- bias table ------------------------------------------------
__global__ void bias_table_kernel(const float* __restrict__ rel_emb) {
    int i = blockIdx.x * blockDim.x + threadIdx.x;
    if (i >= HH * SS) return;
    int h = i / SS;
    int d = i % SS;
    int bucket;
    if (d < 16) {
        bucket = d;
    } else {
        float v = logf((float)d * (1.0f / 16.0f)) / 2.0794415416798357f * 16.0f;
        bucket = 16 + (int)v;
        if (bucket > 31) bucket = 31;
    }
    g_bias[h * SS + d] = rel_emb[bucket * HH + h];
}

// ---------------- RoPE cos/sin table ----------------------------------------
__global__ void rope_table_kernel() {
    int i = blockIdx.x * blockDim.x + threadIdx.x;
    if (i >= SS * 32) return;
    int s = i >> 5;
    int j = i & 31;
    double inv = pow(10000.0, -(double)j / 32.0);
    double a = (double)s * inv;
    g_cos[i] = (float)cos(a);
    g_sin[i] = (float)sin(a);
}

// ================= fp16 tensor-core GEMM (m16n8k16, unchanged) ==============
#define LDAH 72
#define H_TILE (128*LDAH)
#define HSTAGE (2*H_TILE)
#define GEMM_SMEM (HSTAGE * 2 * 2)

__device__ __forceinline__ void gemm_load_stage_h(
    const __half* __restrict__ A, const __half* __restrict__ Bt,
    uint32_t aB, uint32_t bB, int m0, int n0, int k0, int tid)
{
#pragma unroll
    for (int i = 0; i < 4; i++) {
        int s = tid + i * 256;
        int r = s >> 3, cs = s & 7;
        cpasync16(aB + (uint32_t)(r * (LDAH * 2) + cs * 16),
                  A + (size_t)(m0 + r) * DD + k0 + cs * 8);
        cpasync16(bB + (uint32_t)(r * (LDAH * 2) + cs * 16),
                  Bt + (size_t)(n0 + r) * DD + k0 + cs * 8);
    }
}

__device__ __forceinline__ void gemm_body_h(
    const __half* __restrict__ A, const __half* __restrict__ Bt,
    float* __restrict__ Cf, int headLayout, int m0, int n0)
{
    extern __shared__ __half smh[];
    uint32_t smBase = (uint32_t)__cvta_generic_to_shared(smh);
    const int tid  = threadIdx.x;
    const int lane = tid & 31;
    const int wid  = tid >> 5;
    const int gid  = lane >> 2;
    const int tig  = lane & 3;
    const int wm   = (wid >> 2) * 64;
    const int wn   = (wid & 3) * 32;

    float c[4][4][4];
#pragma unroll
    for (int mt = 0; mt < 4; mt++)
#pragma unroll
        for (int nt = 0; nt < 4; nt++)
#pragma unroll
            for (int i = 0; i < 4; i++) c[mt][nt][i] = 0.0f;

    const uint32_t stB = HSTAGE * 2;
    gemm_load_stage_h(A, Bt, smBase, smBase + H_TILE * 2, m0, n0, 0, tid);
    asm volatile("cp.async.commit_group;");

    const int NC = DD / 64;
#pragma unroll 1
    for (int ch = 0; ch < NC; ch++) {
        if (ch + 1 < NC) {
            uint32_t db = smBase + ((ch + 1) & 1) * stB;
            gemm_load_stage_h(A, Bt, db, db + H_TILE * 2, m0, n0, (ch + 1) * 64, tid);
            asm volatile("cp.async.commit_group;");
            asm volatile("cp.async.wait_group 1;");
        } else {
            asm volatile("cp.async.wait_group 0;");
        }
        __syncthreads();

        const uint32_t* Asb = (const uint32_t*)(smh + (ch & 1) * HSTAGE);
        const uint32_t* Bsb = Asb + H_TILE / 2;

#pragma unroll
        for (int ks = 0; ks < 4; ks++) {
            const int kbw = ks * 8;
            uint32_t a[4][4], b[4][2];
#pragma unroll
            for (int mt = 0; mt < 4; mt++) {
                const uint32_t* ap = Asb + (wm + mt * 16 + gid) * (LDAH / 2) + kbw + tig;
                a[mt][0] = ap[0];
                a[mt][1] = ap[8 * (LDAH / 2)];
                a[mt][2] = ap[4];
                a[mt][3] = ap[8 * (LDAH / 2) + 4];
            }
#pragma unroll
            for (int nt = 0; nt < 4; nt++) {
                const uint32_t* bp = Bsb + (wn + nt * 8 + gid) * (LDAH / 2) + kbw + tig;
                b[nt][0] = bp[0];
                b[nt][1] = bp[4];
            }
#pragma unroll
            for (int mt = 0; mt < 4; mt++)
#pragma unroll
                for (int nt = 0; nt < 4; nt++)
                    mma_f16(c[mt][nt], a[mt], b[nt]);
        }
        __syncthreads();
    }

#pragma unroll
    for (int mt = 0; mt < 4; mt++) {
#pragma unroll
        for (int nt = 0; nt < 4; nt++) {
            int row = m0 + wm + mt * 16 + gid;
            int col = n0 + wn + nt * 8 + 2 * tig;
            float2 v0 = make_float2(c[mt][nt][0], c[mt][nt][1]);
            float2 v1 = make_float2(c[mt][nt][2], c[mt][nt][3]);
            if (!headLayout) {
                *(float2*)&Cf[(size_t)row * DD + col] = v0;
                *(float2*)&Cf[(size_t)(row + 8) * DD + col] = v1;
            } else {
                int h = col >> 6, hd = col & 63;
                int b0i = row >> 11, s0 = row & 2047;
                int r1 = row + 8;
                int b1i = r1 >> 11, s1 = r1 & 2047;
                *(float2*)&Cf[(((size_t)(b0i * HH + h)) * SS + s0) * HD + hd] = v0;
                *(float2*)&Cf[(((size_t)(b1i * HH + h)) * SS + s1) * HD + hd] = v1;
            }
        }
    }
}

__global__ __launch_bounds__(256) void gemm_qkv() {
    const int n0g = blockIdx.x * 128;
    const int z   = n0g >> 10;
    const int n0  = n0g & 1023;
    const __half* Bt = g_Wh + (size_t)z * DD * DD;
    float* C = (z == 0) ? g_Q : (z == 1) ? g_K : g_V;
    gemm_body_h(g_xh, Bt, C, 1, blockIdx.y * 128, n0);
}

__global__ __launch_bounds__(256) void gemm_out(float* __restrict__ out) {
    gemm_body_h(g_ctxh, g_Wh + (size_t)3 * DD * DD, out, 0,
                blockIdx.y * 128, blockIdx.x * 128);
}

// ---------------- RoPE: fp32 Q,K -> fp16 g_Qh,g_Kh --------------------------
__global__ void rope_kernel() {
    int gid = blockIdx.x * blockDim.x + threadIdx.x;
    int j   = gid & 31;
    int row = gid >> 5;
    if (row >= BB * HH * SS) return;
    int s = row & (SS - 1);

    float c  = g_cos[s * 32 + j];
    float sn = g_sin[s * 32 + j];

    size_t base = (size_t)row * HD;
    float q0 = g_Q[base + j], q1 = g_Q[base + j + 32];
    g_Qh[base + j]      = __float2half(q0 * c - q1 * sn);
    g_Qh[base + j + 32] = __float2half(q1 * c + q0 * sn);
    float k0 = g_K[base + j], k1 = g_K[base + j + 32];
    g_Kh[base + j]      = __float2half(k0 * c - k1 * sn);
    g_Kh[base + j + 32] = __float2half(k1 * c + k0 * sn);
}

// ---------------- V transpose: fp32 [b,h,s,hd] -> fp16 [b,h,hd,s] -----------
__global__ __launch_bounds__(256) void vtrans_kernel() {
    __shared__ __half ts[64 * 72];
    int bh = blockIdx.y;
    int s0 = blockIdx.x * 64;
    const float* Vg = g_V + (size_t)bh * SS * HD + (size_t)s0 * HD;
#pragma unroll
    for (int i = 0; i < 16; i++) {
        int idx = threadIdx.x + i * 256;
        int r = idx >> 6, cv = idx & 63;
        ts[cv * 72 + r] = __float2half(Vg[r * HD + cv]);
    }
    __syncthreads();
    __half* dst = g_Vth + (size_t)bh * HD * SS + s0;
#pragma unroll
    for (int i = 0; i < 2; i++) {
        int sseg = threadIdx.x + i * 256;
        int j = sseg >> 3, cs = sseg & 7;
        *(uint4*)&dst[(size_t)j * SS + cs * 8] = *(uint4*)&ts[j * 72 + cs * 8];
    }
}

// ============== fp16 tensor-core causal flash attention =====================
// BQ=128, BK=64, 256 threads (8 warps x 16 query rows). m16n8k16 for QK^T, PV.
// P stays in registers (C-fragment == A-fragment layout).
#define ALDSW 36                       // words per smem row (72 halves, padded)
#define KV_TILE (64*ALDSW*2)           // halves per tile: 64 rows * 72
#define ABUF (2*KV_TILE)               // halves per buffer (K + V)
#define ATT_SMEM (2*ABUF*2 + 2*192*4)  // 36864 + 1536 = 38400 bytes

__global__ __launch_bounds__(256) void attn_tc() {
    extern __shared__ __half smh[];
    float* Bw = (float*)(smh + 2 * ABUF);

    const int tid  = threadIdx.x;
    const int lane = tid & 31;
    const int w    = tid >> 5;
    const int gid  = lane >> 2;
    const int tig  = lane & 3;

    const int qt = (gridDim.x - 1) - blockIdx.x;   // long blocks first
    const int h  = blockIdx.y;
    const int b  = blockIdx.z;
    const int q0 = qt * 128;
    const int ktmax = 2 * qt + 1;

    const __half* Qg  = g_Qh  + (size_t)(b * HH + h) * SS * HD;
    const __half* Kg  = g_Kh  + (size_t)(b * HH + h) * SS * HD;
    const __half* Vtg = g_Vth + (size_t)(b * HH + h) * HD * SS;
    const float* biasH = g_bias + h * SS;

    const uint32_t smBase = (uint32_t)__cvta_generic_to_shared(smh);

    auto prefetch = [&](int kt) {
        const int buf = kt & 1;
        const int k0 = kt * 64;
        uint32_t kb = smBase + (uint32_t)(buf * ABUF) * 2;
        uint32_t vb = kb + KV_TILE * 2;
        const __half* KgT = Kg + (size_t)k0 * HD;
        const __half* VgT = Vtg + k0;
#pragma unroll
        for (int i = 0; i < 2; i++) {
            int s = tid + i * 256;          // 512 segs each: 64 rows x 8x16B
            int r = s >> 3, cs = s & 7;
            cpasync16(kb + (uint32_t)(r * 144 + cs * 16), KgT + r * HD + cs * 8);
            cpasync16(vb + (uint32_t)(r * 144 + cs * 16), VgT + (size_t)r * SS + cs * 8);
        }
        int dlo = q0 - k0 - 63;
        if (tid < 192) {
            int d = dlo + tid;
            int ok = (d >= 0 && d < SS) ? 4 : 0;
            int dc = d < 0 ? 0 : (d >= SS ? SS - 1 : d);
            uint32_t dst = smBase + (uint32_t)(2 * ABUF) * 2 + (uint32_t)(buf * 192 + tid) * 4;
            asm volatile("cp.async.ca.shared.global [%0], [%1], 4, %2;"
                         :: "r"(dst), "l"(biasH + dc), "r"(ok));
        }
    };

    prefetch(0);
    asm volatile("cp.async.commit_group;");

    // Q fragments straight from global (one-time, rows row0/row0+8)
    const int qr0 = q0 + 16 * w + gid;
    const uint32_t* q0w = (const uint32_t*)(Qg + (size_t)qr0 * HD);
    const uint32_t* q1w = q0w + 8 * HD / 2;
    uint32_t qa[4][4];
#pragma unroll
    for (int kc = 0; kc < 4; kc++) {
        qa[kc][0] = q0w[kc * 8 + tig];
        qa[kc][1] = q1w[kc * 8 + tig];
        qa[kc][2] = q0w[kc * 8 + tig + 4];
        qa[kc][3] = q1w[kc * 8 + tig + 4];
    }

    float o[8][4];
#pragma unroll
    for (int nt = 0; nt < 8; nt++)
#pragma unroll
        for (int i = 0; i < 4; i++) o[nt][i] = 0.0f;
    float m0 = -1e30f, m1 = -1e30f, l0 = 0.0f, l1 = 0.0f;

    for (int kt = 0; kt <= ktmax; kt++) {
        if (kt < ktmax) {
            prefetch(kt + 1);
            asm volatile("cp.async.commit_group;");
            asm volatile("cp.async.wait_group 1;");
        } else {
            asm volatile("cp.async.wait_group 0;");
        }
        __syncthreads();

        const int k0 = kt * 64;
        const bool active = (k0 <= q0 + 16 * w + 15);
        if (active) {
            const uint32_t* Kw = (const uint32_t*)(smh + (kt & 1) * ABUF);
            const uint32_t* Vw = Kw + KV_TILE / 2;
            const float* bw = Bw + (kt & 1) * 192;
            const int dlo = q0 - k0 - 63;

            // ---- S = Q K^T (fp16 mma, fp32 accum) ----
            float s_[8][4];
#pragma unroll
            for (int nt = 0; nt < 8; nt++)
#pragma unroll
                for (int i = 0; i < 4; i++) s_[nt][i] = 0.0f;

#pragma unroll
            for (int kc = 0; kc < 4; kc++) {
#pragma unroll
                for (int nt = 0; nt < 8; nt++) {
                    const uint32_t* kp = Kw + (nt * 8 + gid) * ALDSW + kc * 8 + tig;
                    uint32_t bf[2] = { kp[0], kp[4] };
                    mma_f16(s_[nt], qa[kc], bf);
                }
            }

            // ---- bias + causal mask + scale; online softmax ----
            const int r0 = qr0, r1 = qr0 + 8;
            const bool needMask = (k0 + 63 > r0);
            float mx0 = m0, mx1 = m1;
#pragma unroll
            for (int nt = 0; nt < 8; nt++) {
                int c0 = k0 + nt * 8 + 2 * tig;
                s_[nt][0] = s_[nt][0] * 0.125f + bw[r0 - c0 - dlo];
                s_[nt][1] = s_[nt][1] * 0.125f + bw[r0 - c0 - 1 - dlo];
                s_[nt][2] = s_[nt][2] * 0.125f + bw[r1 - c0 - dlo];
                s_[nt][3] = s_[nt][3] * 0.125f + bw[r1 - c0 - 1 - dlo];
                if (needMask) {
                    if (c0     > r0) s_[nt][0] = -1e9f;
                    if (c0 + 1 > r0) s_[nt][1] = -1e9f;
                    if (c0     > r1) s_[nt][2] = -1e9f;
                    if (c0 + 1 > r1) s_[nt][3] = -1e9f;
                }
                mx0 = fmaxf(mx0, fmaxf(s_[nt][0], s_[nt][1]));
                mx1 = fmaxf(mx1, fmaxf(s_[nt][2], s_[nt][3]));
            }
            mx0 = fmaxf(mx0, __shfl_xor_sync(0xffffffffu, mx0, 1));
            mx0 = fmaxf(mx0, __shfl_xor_sync(0xffffffffu, mx0, 2));
            mx1 = fmaxf(mx1, __shfl_xor_sync(0xffffffffu, mx1, 1));
            mx1 = fmaxf(mx1, __shfl_xor_sync(0xffffffffu, mx1, 2));

            float corr0 = __expf(m0 - mx0);
            float corr1 = __expf(m1 - mx1);
            m0 = mx0; m1 = mx1;

            uint32_t ph[8][2];
            float ls0 = 0.0f, ls1 = 0.0f;
#pragma unroll
            for (int nt = 0; nt < 8; nt++) {
                float p00 = __expf(s_[nt][0] - mx0);
                float p01 = __expf(s_[nt][1] - mx0);
                float p10 = __expf(s_[nt][2] - mx1);
                float p11 = __expf(s_[nt][3] - mx1);
                ls0 += p00 + p01;
                ls1 += p10 + p11;
                __half2 hp0 = __floats2half2_rn(p00, p01);
                __half2 hp1 = __floats2half2_rn(p10, p11);
                ph[nt][0] = *(uint32_t*)&hp0;
                ph[nt][1] = *(uint32_t*)&hp1;
                o[nt][0] *= corr0; o[nt][1] *= corr0;
                o[nt][2] *= corr1; o[nt][3] *= corr1;
            }
            ls0 += __shfl_xor_sync(0xffffffffu, ls0, 1);
            ls0 += __shfl_xor_sync(0xffffffffu, ls0, 2);
            ls1 += __shfl_xor_sync(0xffffffffu, ls1, 1);
            ls1 += __shfl_xor_sync(0xffffffffu, ls1, 2);
            l0 = l0 * corr0 + ls0;
            l1 = l1 * corr1 + ls1;

            // ---- O += P V  (P fragments direct from registers) ----
#pragma unroll
            for (int kc = 0; kc < 4; kc++) {
                uint32_t pa[4] = { ph[2 * kc][0], ph[2 * kc][1],
                                   ph[2 * kc + 1][0], ph[2 * kc + 1][1] };
#pragma unroll
                for (int nt = 0; nt < 8; nt++) {
                    const uint32_t* vp = Vw + (nt * 8 + gid) * ALDSW + kc * 8 + tig;
                    uint32_t bf[2] = { vp[0], vp[4] };
                    mma_f16(o[nt], pa, bf);
                }
            }
        }
        __syncthreads();
    }

    // epilogue: ctx emitted as fp16 (feeds fp16 Wo GEMM)
    const float inv0 = 1.0f / l0;
    const float inv1 = 1.0f / l1;
    const int hbase = h * HD;
#pragma unroll
    for (int nt = 0; nt < 8; nt++) {
        int c = hbase + nt * 8 + 2 * tig;
        *(__half2*)&g_ctxh[((size_t)b * SS + qr0) * DD + c] =
            __floats2half2_rn(o[nt][0] * inv0, o[nt][1] * inv0);
        *(__half2*)&g_ctxh[((size_t)b * SS + qr0 + 8) * DD + c] =
            __floats2half2_rn(o[nt][2] * inv1, o[nt][3] * inv1);
    }
}

// ---------------- launcher --------------------------------------------------
extern "C" void kernel_launch(void* const* d_in, const int* in_sizes, int n_in,
                              void* d_out, int out_size)
{
    const float* x   = (const float*)d_in[0];
    const float* Wq  = (const float*)d_in[1];
    const float* Wk  = (const float*)d_in[2];
    const float* Wv  = (const float*)d_in[3];
    const float* Wo  = (const float*)d_in[4];
    const float* rel = (const float*)d_in[5];
    float* out = (float*)d_out;

    __half* xh;
    cudaGetSymbolAddress((void**)&xh, g_xh);

    cudaFuncSetAttribute(gemm_qkv, cudaFuncAttributeMaxDynamicSharedMemorySize, GEMM_SMEM);
    cudaFuncSetAttribute(gemm_out, cudaFuncAttributeMaxDynamicSharedMemorySize, GEMM_SMEM);
    cudaFuncSetAttribute(attn_tc, cudaFuncAttributeMaxDynamicSharedMemorySize, ATT_SMEM);

    // 1) setup tables + fp16 conversion of inputs
    bias_table_kernel<<<(HH * SS + 255) / 256, 256>>>(rel);
    rope_table_kernel<<<(SS * 32 + 255) / 256, 256>>>();
    to_half_kernel<<<(MROWS * DD / 4 + 255) / 256, 256>>>(x, xh, MROWS * DD);
    transpose_half_kernel<<<dim3(DD / 32, DD / 32, 4), dim3(32, 8)>>>(Wq, Wk, Wv, Wo);

    // 2) fused QKV projections, fp16 tensor cores -> fp32 [B,H,S,HD]
    gemm_qkv<<<dim3(3 * DD / 128, MROWS / 128), 256, GEMM_SMEM>>>();

    // 3) RoPE -> fp16 Q,K ; V transpose -> fp16 [b,h,hd,s]
    rope_kernel<<<(BB * HH * SS * 32) / 256, 256>>>();
    vtrans_kernel<<<dim3(SS / 64, BB * HH), 256>>>();

    // 4) fp16 tensor-core causal attention with bias
    attn_tc<<<dim3(SS / 128, HH, BB), 256, ATT_SMEM>>>();

    // 5) output projection, fp16 tensor cores
    gemm_out<<<dim3(DD / 128, MROWS / 128), 256, GEMM_SMEM>>>(out);
}

// round 16
// speedup vs baseline: 7.7065x; 1.0529x over previous
#include <cuda_runtime.h>
#include <cuda_fp16.h>
#include <math.h>
#include <stdint.h>

#define BB 2
#define SS 2048
#define DD 1024
#define HH 16
#define HD 64
#define MROWS (BB*SS)   // 4096

// ---------------- scratch (device globals; no allocations allowed) ----------
__device__ float  g_Q[BB*HH*SS*HD];     // fp32 pre-rope QKV from GEMM
__device__ float  g_K[BB*HH*SS*HD];
__device__ float  g_V[BB*HH*SS*HD];
__device__ __half g_Qh[BB*HH*SS*HD];    // fp16 post-rope Q [b,h,s,hd]
__device__ __half g_Kh[BB*HH*SS*HD];    // fp16 post-rope K [b,h,s,hd]
__device__ __half g_Vth[BB*HH*HD*SS];   // fp16 V TRANSPOSED [b,h,hd,s]
__device__ __half g_ctxh[MROWS*DD];
__device__ float  g_bias[HH*SS];        // bias[h][distance], distance = q-k >= 0
__device__ float  g_cos[SS*32];
__device__ float  g_sin[SS*32];
__device__ __half g_xh[MROWS*DD];       // fp16 x
__device__ __half g_Wh[4*DD*DD];        // fp16 TRANSPOSED Wq,Wk,Wv,Wo ([N][K])

// ---------------- common PTX helpers ----------------------------------------
__device__ __forceinline__ void cpasync16(uint32_t s, const void* g) {
    asm volatile("cp.async.cg.shared.global [%0], [%1], 16;" :: "r"(s), "l"(g));
}
__device__ __forceinline__ void mma_f16(float* c, const uint32_t* a, const uint32_t* b) {
    asm volatile(
        "mma.sync.aligned.m16n8k16.row.col.f32.f16.f16.f32 "
        "{%0,%1,%2,%3},{%4,%5,%6,%7},{%8,%9},{%0,%1,%2,%3};"
        : "+f"(c[0]), "+f"(c[1]), "+f"(c[2]), "+f"(c[3])
        : "r"(a[0]), "r"(a[1]), "r"(a[2]), "r"(a[3]), "r"(b[0]), "r"(b[1]));
}
__device__ __forceinline__ void ldsm_x4(uint32_t& r0, uint32_t& r1,
                                        uint32_t& r2, uint32_t& r3, uint32_t addr) {
    asm volatile("ldmatrix.sync.aligned.m8n8.x4.shared.b16 {%0,%1,%2,%3}, [%4];"
                 : "=r"(r0), "=r"(r1), "=r"(r2), "=r"(r3) : "r"(addr));
}

// ---------------- x -> fp16 -------------------------------------------------
__global__ void to_half_kernel(const float* __restrict__ src,
                               __half* __restrict__ dst, int n) {
    int i = (blockIdx.x * blockDim.x + threadIdx.x) * 4;
    if (i >= n) return;
    float4 v = *(const float4*)(src + i);
    *(__half2*)(dst + i)     = __floats2half2_rn(v.x, v.y);
    *(__half2*)(dst + i + 2) = __floats2half2_rn(v.z, v.w);
}

// ---------------- W transpose + fp16: g_Wh[z][n][k] = (half)W[k][n] ---------
__global__ void transpose_half_kernel(const float* __restrict__ W0,
                                      const float* __restrict__ W1,
                                      const float* __restrict__ W2,
                                      const float* __restrict__ W3) {
    __shared__ float t[32][33];
    const float* W = (blockIdx.z == 0) ? W0 : (blockIdx.z == 1) ? W1
                   : (blockIdx.z == 2) ? W2 : W3;
    __half* Wt = g_Wh + (size_t)blockIdx.z * DD * DD;
    int bn = blockIdx.x * 32;
    int bk = blockIdx.y * 32;
    int tx = threadIdx.x, ty = threadIdx.y;
#pragma unroll
    for (int i = 0; i < 4; i++)
        t[ty + 8 * i][tx] = W[(size_t)(bk + ty + 8 * i) * DD + bn + tx];
    __syncthreads();
#pragma unroll
    for (int i = 0; i < 4; i++)
        Wt[(size_t)(bn + ty + 8 * i) * DD + bk + tx] = __float2half(t[tx][ty + 8 * i]);
}

// ---------------- bias table ------------------------------------------------
__global__ void bias_table_kernel(const float* __restrict__ rel_emb) {
    int i = blockIdx.x * blockDim.x + threadIdx.x;
    if (i >= HH * SS) return;
    int h = i / SS;
    int d = i % SS;
    int bucket;
    if (d < 16) {
        bucket = d;
    } else {
        float v = logf((float)d * (1.0f / 16.0f)) / 2.0794415416798357f * 16.0f;
        bucket = 16 + (int)v;
        if (bucket > 31) bucket = 31;
    }
    g_bias[h * SS + d] = rel_emb[bucket * HH + h];
}

// ---------------- RoPE cos/sin table ----------------------------------------
__global__ void rope_table_kernel() {
    int i = blockIdx.x * blockDim.x + threadIdx.x;
    if (i >= SS * 32) return;
    int s = i >> 5;
    int j = i & 31;
    double inv = pow(10000.0, -(double)j / 32.0);
    double a = (double)s * inv;
    g_cos[i] = (float)cos(a);
    g_sin[i] = (float)sin(a);
}

// ================= fp16 tensor-core GEMM (m16n8k16 + ldmatrix) ==============
#define LDAH 72
#define H_TILE (128*LDAH)
#define HSTAGE (2*H_TILE)
#define GEMM_SMEM (HSTAGE * 2 * 2)

__device__ __forceinline__ void gemm_load_stage_h(
    const __half* __restrict__ A, const __half* __restrict__ Bt,
    uint32_t aB, uint32_t bB, int m0, int n0, int k0, int tid)
{
#pragma unroll
    for (int i = 0; i < 4; i++) {
        int s = tid + i * 256;
        int r = s >> 3, cs = s & 7;
        cpasync16(aB + (uint32_t)(r * (LDAH * 2) + cs * 16),
                  A + (size_t)(m0 + r) * DD + k0 + cs * 8);
        cpasync16(bB + (uint32_t)(r * (LDAH * 2) + cs * 16),
                  Bt + (size_t)(n0 + r) * DD + k0 + cs * 8);
    }
}

__device__ __forceinline__ void gemm_body_h(
    const __half* __restrict__ A, const __half* __restrict__ Bt,
    float* __restrict__ Cf, int headLayout, int m0, int n0)
{
    extern __shared__ __half smh[];
    uint32_t smBase = (uint32_t)__cvta_generic_to_shared(smh);
    const int tid  = threadIdx.x;
    const int lane = tid & 31;
    const int wid  = tid >> 5;
    const int gid  = lane >> 2;
    const int tig  = lane & 3;
    const int wm   = (wid >> 2) * 64;
    const int wn   = (wid & 3) * 32;

    // ldmatrix lane address components
    const int lrow  = lane & 15;            // A: row within 16
    const int lsel  = (lane >> 4) << 3;     // A: 0/8 half-col select; B: row-pair select
    const int brow  = lsel + (lane & 7);    // B: row within 16
    const int bcolh = ((lane >> 3) & 1) << 3;  // B: 0/8 half-col select

    float c[4][4][4];
#pragma unroll
    for (int mt = 0; mt < 4; mt++)
#pragma unroll
        for (int nt = 0; nt < 4; nt++)
#pragma unroll
            for (int i = 0; i < 4; i++) c[mt][nt][i] = 0.0f;

    const uint32_t stB = HSTAGE * 2;
    gemm_load_stage_h(A, Bt, smBase, smBase + H_TILE * 2, m0, n0, 0, tid);
    asm volatile("cp.async.commit_group;");

    const int NC = DD / 64;
#pragma unroll 1
    for (int ch = 0; ch < NC; ch++) {
        if (ch + 1 < NC) {
            uint32_t db = smBase + ((ch + 1) & 1) * stB;
            gemm_load_stage_h(A, Bt, db, db + H_TILE * 2, m0, n0, (ch + 1) * 64, tid);
            asm volatile("cp.async.commit_group;");
            asm volatile("cp.async.wait_group 1;");
        } else {
            asm volatile("cp.async.wait_group 0;");
        }
        __syncthreads();

        const uint32_t aStage = smBase + ((ch & 1) ? stB : 0u);
        const uint32_t bStage = aStage + H_TILE * 2;

#pragma unroll
        for (int ks = 0; ks < 4; ks++) {
            const int khalf = ks * 16;
            uint32_t a[4][4], b[4][2];
#pragma unroll
            for (int mt = 0; mt < 4; mt++) {
                uint32_t ad = aStage +
                    (uint32_t)(((wm + mt * 16 + lrow) * LDAH + khalf + lsel) * 2);
                ldsm_x4(a[mt][0], a[mt][1], a[mt][2], a[mt][3], ad);
            }
#pragma unroll
            for (int np = 0; np < 2; np++) {
                uint32_t bd = bStage +
                    (uint32_t)(((wn + np * 16 + brow) * LDAH + khalf + bcolh) * 2);
                ldsm_x4(b[2 * np][0], b[2 * np][1], b[2 * np + 1][0], b[2 * np + 1][1], bd);
            }
#pragma unroll
            for (int mt = 0; mt < 4; mt++)
#pragma unroll
                for (int nt = 0; nt < 4; nt++)
                    mma_f16(c[mt][nt], a[mt], b[nt]);
        }
        __syncthreads();
    }

#pragma unroll
    for (int mt = 0; mt < 4; mt++) {
#pragma unroll
        for (int nt = 0; nt < 4; nt++) {
            int row = m0 + wm + mt * 16 + gid;
            int col = n0 + wn + nt * 8 + 2 * tig;
            float2 v0 = make_float2(c[mt][nt][0], c[mt][nt][1]);
            float2 v1 = make_float2(c[mt][nt][2], c[mt][nt][3]);
            if (!headLayout) {
                *(float2*)&Cf[(size_t)row * DD + col] = v0;
                *(float2*)&Cf[(size_t)(row + 8) * DD + col] = v1;
            } else {
                int h = col >> 6, hd = col & 63;
                int b0i = row >> 11, s0 = row & 2047;
                int r1 = row + 8;
                int b1i = r1 >> 11, s1 = r1 & 2047;
                *(float2*)&Cf[(((size_t)(b0i * HH + h)) * SS + s0) * HD + hd] = v0;
                *(float2*)&Cf[(((size_t)(b1i * HH + h)) * SS + s1) * HD + hd] = v1;
            }
        }
    }
}

__global__ __launch_bounds__(256) void gemm_qkv() {
    const int n0g = blockIdx.x * 128;
    const int z   = n0g >> 10;
    const int n0  = n0g & 1023;
    const __half* Bt = g_Wh + (size_t)z * DD * DD;
    float* C = (z == 0) ? g_Q : (z == 1) ? g_K : g_V;
    gemm_body_h(g_xh, Bt, C, 1, blockIdx.y * 128, n0);
}

__global__ __launch_bounds__(256) void gemm_out(float* __restrict__ out) {
    gemm_body_h(g_ctxh, g_Wh + (size_t)3 * DD * DD, out, 0,
                blockIdx.y * 128, blockIdx.x * 128);
}

// ---------------- RoPE: fp32 Q,K -> fp16 g_Qh,g_Kh --------------------------
__global__ void rope_kernel() {
    int gid = blockIdx.x * blockDim.x + threadIdx.x;
    int j   = gid & 31;
    int row = gid >> 5;
    if (row >= BB * HH * SS) return;
    int s = row & (SS - 1);

    float c  = g_cos[s * 32 + j];
    float sn = g_sin[s * 32 + j];

    size_t base = (size_t)row * HD;
    float q0 = g_Q[base + j], q1 = g_Q[base + j + 32];
    g_Qh[base + j]      = __float2half(q0 * c - q1 * sn);
    g_Qh[base + j + 32] = __float2half(q1 * c + q0 * sn);
    float k0 = g_K[base + j], k1 = g_K[base + j + 32];
    g_Kh[base + j]      = __float2half(k0 * c - k1 * sn);
    g_Kh[base + j + 32] = __float2half(k1 * c + k0 * sn);
}

// ---------------- V transpose: fp32 [b,h,s,hd] -> fp16 [b,h,hd,s] -----------
__global__ __launch_bounds__(256) void vtrans_kernel() {
    __shared__ __half ts[64 * 72];
    int bh = blockIdx.y;
    int s0 = blockIdx.x * 64;
    const float* Vg = g_V + (size_t)bh * SS * HD + (size_t)s0 * HD;
#pragma unroll
    for (int i = 0; i < 16; i++) {
        int idx = threadIdx.x + i * 256;
        int r = idx >> 6, cv = idx & 63;
        ts[cv * 72 + r] = __float2half(Vg[r * HD + cv]);
    }
    __syncthreads();
    __half* dst = g_Vth + (size_t)bh * HD * SS + s0;
#pragma unroll
    for (int i = 0; i < 2; i++) {
        int sseg = threadIdx.x + i * 256;
        int j = sseg >> 3, cs = sseg & 7;
        *(uint4*)&dst[(size_t)j * SS + cs * 8] = *(uint4*)&ts[j * 72 + cs * 8];
    }
}

// ============== fp16 tensor-core causal flash attention (ldmatrix) ==========
#define ALDSW 36
#define KV_TILE (64*ALDSW*2)
#define ABUF (2*KV_TILE)
#define ATT_SMEM (2*ABUF*2 + 2*192*4)

__global__ __launch_bounds__(256) void attn_tc() {
    extern __shared__ __half smh[];
    float* Bw = (float*)(smh + 2 * ABUF);

    const int tid  = threadIdx.x;
    const int lane = tid & 31;
    const int w    = tid >> 5;
    const int gid  = lane >> 2;
    const int tig  = lane & 3;

    // ldmatrix B-style lane address components (same as GEMM)
    const int lsel  = (lane >> 4) << 3;
    const int brow  = lsel + (lane & 7);
    const int bcolh = ((lane >> 3) & 1) << 3;

    const int qt = (gridDim.x - 1) - blockIdx.x;
    const int h  = blockIdx.y;
    const int b  = blockIdx.z;
    const int q0 = qt * 128;
    const int ktmax = 2 * qt + 1;

    const __half* Qg  = g_Qh  + (size_t)(b * HH + h) * SS * HD;
    const __half* Kg  = g_Kh  + (size_t)(b * HH + h) * SS * HD;
    const __half* Vtg = g_Vth + (size_t)(b * HH + h) * HD * SS;
    const float* biasH = g_bias + h * SS;

    const uint32_t smBase = (uint32_t)__cvta_generic_to_shared(smh);

    auto prefetch = [&](int kt) {
        const int buf = kt & 1;
        const int k0 = kt * 64;
        uint32_t kb = smBase + (uint32_t)(buf * ABUF) * 2;
        uint32_t vb = kb + KV_TILE * 2;
        const __half* KgT = Kg + (size_t)k0 * HD;
        const __half* VgT = Vtg + k0;
#pragma unroll
        for (int i = 0; i < 2; i++) {
            int s = tid + i * 256;
            int r = s >> 3, cs = s & 7;
            cpasync16(kb + (uint32_t)(r * 144 + cs * 16), KgT + r * HD + cs * 8);
            cpasync16(vb + (uint32_t)(r * 144 + cs * 16), VgT + (size_t)r * SS + cs * 8);
        }
        int dlo = q0 - k0 - 63;
        if (tid < 192) {
            int d = dlo + tid;
            int ok = (d >= 0 && d < SS) ? 4 : 0;
            int dc = d < 0 ? 0 : (d >= SS ? SS - 1 : d);
            uint32_t dst = smBase + (uint32_t)(2 * ABUF) * 2 + (uint32_t)(buf * 192 + tid) * 4;
            asm volatile("cp.async.ca.shared.global [%0], [%1], 4, %2;"
                         :: "r"(dst), "l"(biasH + dc), "r"(ok));
        }
    };

    prefetch(0);
    asm volatile("cp.async.commit_group;");

    const int qr0 = q0 + 16 * w + gid;
    const uint32_t* q0w = (const uint32_t*)(Qg + (size_t)qr0 * HD);
    const uint32_t* q1w = q0w + 8 * HD / 2;
    uint32_t qa[4][4];
#pragma unroll
    for (int kc = 0; kc < 4; kc++) {
        qa[kc][0] = q0w[kc * 8 + tig];
        qa[kc][1] = q1w[kc * 8 + tig];
        qa[kc][2] = q0w[kc * 8 + tig + 4];
        qa[kc][3] = q1w[kc * 8 + tig + 4];
    }

    float o[8][4];
#pragma unroll
    for (int nt = 0; nt < 8; nt++)
#pragma unroll
        for (int i = 0; i < 4; i++) o[nt][i] = 0.0f;
    float m0 = -1e30f, m1 = -1e30f, l0 = 0.0f, l1 = 0.0f;

    for (int kt = 0; kt <= ktmax; kt++) {
        if (kt < ktmax) {
            prefetch(kt + 1);
            asm volatile("cp.async.commit_group;");
            asm volatile("cp.async.wait_group 1;");
        } else {
            asm volatile("cp.async.wait_group 0;");
        }
        __syncthreads();

        const int k0 = kt * 64;
        const bool active = (k0 <= q0 + 16 * w + 15);
        if (active) {
            const uint32_t kStage = smBase + (uint32_t)((kt & 1) * ABUF) * 2;
            const uint32_t vStage = kStage + KV_TILE * 2;
            const float* bw = Bw + (kt & 1) * 192;
            const int dlo = q0 - k0 - 63;

            // ---- S = Q K^T (ldmatrix fragments) ----
            float s_[8][4];
#pragma unroll
            for (int nt = 0; nt < 8; nt++)
#pragma unroll
                for (int i = 0; i < 4; i++) s_[nt][i] = 0.0f;

#pragma unroll
            for (int kc = 0; kc < 4; kc++) {
                const int khalf = kc * 16;
#pragma unroll
                for (int p = 0; p < 4; p++) {
                    uint32_t kd = kStage +
                        (uint32_t)(((p * 16 + brow) * (ALDSW * 2) + khalf + bcolh) * 2);
                    uint32_t t0, t1, t2, t3;
                    ldsm_x4(t0, t1, t2, t3, kd);
                    uint32_t bf0[2] = { t0, t1 };
                    uint32_t bf1[2] = { t2, t3 };
                    mma_f16(s_[2 * p], qa[kc], bf0);
                    mma_f16(s_[2 * p + 1], qa[kc], bf1);
                }
            }

            // ---- bias + causal mask + scale; online softmax ----
            const int r0 = qr0, r1 = qr0 + 8;
            const bool needMask = (k0 + 63 > r0);
            float mx0 = m0, mx1 = m1;
#pragma unroll
            for (int nt = 0; nt < 8; nt++) {
                int c0 = k0 + nt * 8 + 2 * tig;
                s_[nt][0] = s_[nt][0] * 0.125f + bw[r0 - c0 - dlo];
                s_[nt][1] = s_[nt][1] * 0.125f + bw[r0 - c0 - 1 - dlo];
                s_[nt][2] = s_[nt][2] * 0.125f + bw[r1 - c0 - dlo];
                s_[nt][3] = s_[nt][3] * 0.125f + bw[r1 - c0 - 1 - dlo];
                if (needMask) {
                    if (c0     > r0) s_[nt][0] = -1e9f;
                    if (c0 + 1 > r0) s_[nt][1] = -1e9f;
                    if (c0     > r1) s_[nt][2] = -1e9f;
                    if (c0 + 1 > r1) s_[nt][3] = -1e9f;
                }
                mx0 = fmaxf(mx0, fmaxf(s_[nt][0], s_[nt][1]));
                mx1 = fmaxf(mx1, fmaxf(s_[nt][2], s_[nt][3]));
            }
            mx0 = fmaxf(mx0, __shfl_xor_sync(0xffffffffu, mx0, 1));
            mx0 = fmaxf(mx0, __shfl_xor_sync(0xffffffffu, mx0, 2));
            mx1 = fmaxf(mx1, __shfl_xor_sync(0xffffffffu, mx1, 1));
            mx1 = fmaxf(mx1, __shfl_xor_sync(0xffffffffu, mx1, 2));

            float corr0 = __expf(m0 - mx0);
            float corr1 = __expf(m1 - mx1);
            m0 = mx0; m1 = mx1;

            uint32_t ph[8][2];
            float ls0 = 0.0f, ls1 = 0.0f;
#pragma unroll
            for (int nt = 0; nt < 8; nt++) {
                float p00 = __expf(s_[nt][0] - mx0);
                float p01 = __expf(s_[nt][1] - mx0);
                float p10 = __expf(s_[nt][2] - mx1);
                float p11 = __expf(s_[nt][3] - mx1);
                ls0 += p00 + p01;
                ls1 += p10 + p11;
                __half2 hp0 = __floats2half2_rn(p00, p01);
                __half2 hp1 = __floats2half2_rn(p10, p11);
                ph[nt][0] = *(uint32_t*)&hp0;
                ph[nt][1] = *(uint32_t*)&hp1;
                o[nt][0] *= corr0; o[nt][1] *= corr0;
                o[nt][2] *= corr1; o[nt][3] *= corr1;
            }
            ls0 += __shfl_xor_sync(0xffffffffu, ls0, 1);
            ls0 += __shfl_xor_sync(0xffffffffu, ls0, 2);
            ls1 += __shfl_xor_sync(0xffffffffu, ls1, 1);
            ls1 += __shfl_xor_sync(0xffffffffu, ls1, 2);
            l0 = l0 * corr0 + ls0;
            l1 = l1 * corr1 + ls1;

            // ---- O += P V (register P, ldmatrix V) ----
#pragma unroll
            for (int kc = 0; kc < 4; kc++) {
                const int khalf = kc * 16;
                uint32_t pa[4] = { ph[2 * kc][0], ph[2 * kc][1],
                                   ph[2 * kc + 1][0], ph[2 * kc + 1][1] };
#pragma unroll
                for (int p = 0; p < 4; p++) {
                    uint32_t vd = vStage +
                        (uint32_t)(((p * 16 + brow) * (ALDSW * 2) + khalf + bcolh) * 2);
                    uint32_t t0, t1, t2, t3;
                    ldsm_x4(t0, t1, t2, t3, vd);
                    uint32_t bf0[2] = { t0, t1 };
                    uint32_t bf1[2] = { t2, t3 };
                    mma_f16(o[2 * p], pa, bf0);
                    mma_f16(o[2 * p + 1], pa, bf1);
                }
            }
        }
        __syncthreads();
    }

    const float inv0 = 1.0f / l0;
    const float inv1 = 1.0f / l1;
    const int hbase = h * HD;
#pragma unroll
    for (int nt = 0; nt < 8; nt++) {
        int c = hbase + nt * 8 + 2 * tig;
        *(__half2*)&g_ctxh[((size_t)b * SS + qr0) * DD + c] =
            __floats2half2_rn(o[nt][0] * inv0, o[nt][1] * inv0);
        *(__half2*)&g_ctxh[((size_t)b * SS + qr0 + 8) * DD + c] =
            __floats2half2_rn(o[nt][2] * inv1, o[nt][3] * inv1);
    }
}

// ---------------- launcher --------------------------------------------------
extern "C" void kernel_launch(void* const* d_in, const int* in_sizes, int n_in,
                              void* d_out, int out_size)
{
    const float* x   = (const float*)d_in[0];
    const float* Wq  = (const float*)d_in[1];
    const float* Wk  = (const float*)d_in[2];
    const float* Wv  = (const float*)d_in[3];
    const float* Wo  = (const float*)d_in[4];
    const float* rel = (const float*)d_in[5];
    float* out = (float*)d_out;

    __half* xh;
    cudaGetSymbolAddress((void**)&xh, g_xh);

    cudaFuncSetAttribute(gemm_qkv, cudaFuncAttributeMaxDynamicSharedMemorySize, GEMM_SMEM);
    cudaFuncSetAttribute(gemm_out, cudaFuncAttributeMaxDynamicSharedMemorySize, GEMM_SMEM);
    cudaFuncSetAttribute(attn_tc, cudaFuncAttributeMaxDynamicSharedMemorySize, ATT_SMEM);

    // 1) setup tables + fp16 conversion of inputs
    bias_table_kernel<<<(HH * SS + 255) / 256, 256>>>(rel);
    rope_table_kernel<<<(SS * 32 + 255) / 256, 256>>>();
    to_half_kernel<<<(MROWS * DD / 4 + 255) / 256, 256>>>(x, xh, MROWS * DD);
    transpose_half_kernel<<<dim3(DD / 32, DD / 32, 4), dim3(32, 8)>>>(Wq, Wk, Wv, Wo);

    // 2) fused QKV projections, fp16 tensor cores -> fp32 [B,H,S,HD]
    gemm_qkv<<<dim3(3 * DD / 128, MROWS / 128), 256, GEMM_SMEM>>>();

    // 3) RoPE -> fp16 Q,K ; V transpose -> fp16 [b,h,hd,s]
    rope_kernel<<<(BB * HH * SS * 32) / 256, 256>>>();
    vtrans_kernel<<<dim3(SS / 64, BB * HH), 256>>>();

    // 4) fp16 tensor-core causal attention with bias (ldmatrix fragments)
    attn_tc<<<dim3(SS / 128, HH, BB), 256, ATT_SMEM>>>();

    // 5) output projection, fp16 tensor cores
    gemm_out<<<dim3(DD / 128, MROWS / 128), 256, GEMM_SMEM>>>(out);
}

// round 17
// speedup vs baseline: 7.7074x; 1.0001x over previous
#include <cuda_runtime.h>
#include <cuda_fp16.h>
#include <math.h>
#include <stdint.h>

#define BB 2
#define SS 2048
#define DD 1024
#define HH 16
#define HD 64
#define MROWS (BB*SS)   // 4096

// ---------------- scratch (device globals; no allocations allowed) ----------
__device__ __half g_Qh[BB*HH*SS*HD];    // fp16 post-rope Q [b,h,s,hd]
__device__ __half g_Kh[BB*HH*SS*HD];    // fp16 post-rope K [b,h,s,hd]
__device__ __half g_Vth[BB*HH*HD*SS];   // fp16 V TRANSPOSED [b,h,hd,s]
__device__ __half g_ctxh[MROWS*DD];
__device__ float  g_bias[HH*SS];        // bias[h][distance], distance = q-k >= 0
__device__ float  g_cos[SS*32];
__device__ float  g_sin[SS*32];
__device__ __half g_xh[MROWS*DD];       // fp16 x
__device__ __half g_Wh[4*DD*DD];        // fp16 TRANSPOSED Wq,Wk,Wv,Wo ([N][K])

// ---------------- common PTX helpers ----------------------------------------
__device__ __forceinline__ void cpasync16(uint32_t s, const void* g) {
    asm volatile("cp.async.cg.shared.global [%0], [%1], 16;" :: "r"(s), "l"(g));
}
__device__ __forceinline__ void mma_f16(float* c, const uint32_t* a, const uint32_t* b) {
    asm volatile(
        "mma.sync.aligned.m16n8k16.row.col.f32.f16.f16.f32 "
        "{%0,%1,%2,%3},{%4,%5,%6,%7},{%8,%9},{%0,%1,%2,%3};"
        : "+f"(c[0]), "+f"(c[1]), "+f"(c[2]), "+f"(c[3])
        : "r"(a[0]), "r"(a[1]), "r"(a[2]), "r"(a[3]), "r"(b[0]), "r"(b[1]));
}
__device__ __forceinline__ void ldsm_x4(uint32_t& r0, uint32_t& r1,
                                        uint32_t& r2, uint32_t& r3, uint32_t addr) {
    asm volatile("ldmatrix.sync.aligned.m8n8.x4.shared.b16 {%0,%1,%2,%3}, [%4];"
                 : "=r"(r0), "=r"(r1), "=r"(r2), "=r"(r3) : "r"(addr));
}

// ---------------- x -> fp16 -------------------------------------------------
__global__ void to_half_kernel(const float* __restrict__ src,
                               __half* __restrict__ dst, int n) {
    int i = (blockIdx.x * blockDim.x + threadIdx.x) * 4;
    if (i >= n) return;
    float4 v = *(const float4*)(src + i);
    *(__half2*)(dst + i)     = __floats2half2_rn(v.x, v.y);
    *(__half2*)(dst + i + 2) = __floats2half2_rn(v.z, v.w);
}

// ---------------- W transpose + fp16: g_Wh[z][n][k] = (half)W[k][n] ---------
__global__ void transpose_half_kernel(const float* __restrict__ W0,
                                      const float* __restrict__ W1,
                                      const float* __restrict__ W2,
                                      const float* __restrict__ W3) {
    __shared__ float t[32][33];
    const float* W = (blockIdx.z == 0) ? W0 : (blockIdx.z == 1) ? W1
                   : (blockIdx.z == 2) ? W2 : W3;
    __half* Wt = g_Wh + (size_t)blockIdx.z * DD * DD;
    int bn = blockIdx.x * 32;
    int bk = blockIdx.y * 32;
    int tx = threadIdx.x, ty = threadIdx.y;
#pragma unroll
    for (int i = 0; i < 4; i++)
        t[ty + 8 * i][tx] = W[(size_t)(bk + ty + 8 * i) * DD + bn + tx];
    __syncthreads();
#pragma unroll
    for (int i = 0; i < 4; i++)
        Wt[(size_t)(bn + ty + 8 * i) * DD + bk + tx] = __float2half(t[tx][ty + 8 * i]);
}

// ---------------- bias table ------------------------------------------------
__global__ void bias_table_kernel(const float* __restrict__ rel_emb) {
    int i = blockIdx.x * blockDim.x + threadIdx.x;
    if (i >= HH * SS) return;
    int h = i / SS;
    int d = i % SS;
    int bucket;
    if (d < 16) {
        bucket = d;
    } else {
        float v = logf((float)d * (1.0f / 16.0f)) / 2.0794415416798357f * 16.0f;
        bucket = 16 + (int)v;
        if (bucket > 31) bucket = 31;
    }
    g_bias[h * SS + d] = rel_emb[bucket * HH + h];
}

// ---------------- RoPE cos/sin table ----------------------------------------
__global__ void rope_table_kernel() {
    int i = blockIdx.x * blockDim.x + threadIdx.x;
    if (i >= SS * 32) return;
    int s = i >> 5;
    int j = i & 31;
    double inv = pow(10000.0, -(double)j / 32.0);
    double a = (double)s * inv;
    g_cos[i] = (float)cos(a);
    g_sin[i] = (float)sin(a);
}

// ================= fp16 tensor-core GEMM (m16n8k16 + ldmatrix) ==============
// mode: 0 = plain fp32 C store; 1 = Q rope->g_Qh; 2 = K rope->g_Kh;
//       3 = V transpose->g_Vth
#define LDAH 72
#define H_TILE (128*LDAH)
#define HSTAGE (2*H_TILE)
#define GEMM_SMEM (HSTAGE * 2 * 2)   // 73728 bytes; staging tile 128*129*4=66048 fits
#define STLD 129

__device__ __forceinline__ void gemm_load_stage_h(
    const __half* __restrict__ A, const __half* __restrict__ Bt,
    uint32_t aB, uint32_t bB, int m0, int n0, int k0, int tid)
{
#pragma unroll
    for (int i = 0; i < 4; i++) {
        int s = tid + i * 256;
        int r = s >> 3, cs = s & 7;
        cpasync16(aB + (uint32_t)(r * (LDAH * 2) + cs * 16),
                  A + (size_t)(m0 + r) * DD + k0 + cs * 8);
        cpasync16(bB + (uint32_t)(r * (LDAH * 2) + cs * 16),
                  Bt + (size_t)(n0 + r) * DD + k0 + cs * 8);
    }
}

__device__ __forceinline__ void gemm_body_h(
    const __half* __restrict__ A, const __half* __restrict__ Bt,
    float* __restrict__ Cf, int mode, int m0, int n0)
{
    extern __shared__ __half smh[];
    uint32_t smBase = (uint32_t)__cvta_generic_to_shared(smh);
    const int tid  = threadIdx.x;
    const int lane = tid & 31;
    const int wid  = tid >> 5;
    const int gid  = lane >> 2;
    const int tig  = lane & 3;
    const int wm   = (wid >> 2) * 64;
    const int wn   = (wid & 3) * 32;

    // ldmatrix lane address components
    const int lrow  = lane & 15;
    const int lsel  = (lane >> 4) << 3;
    const int brow  = lsel + (lane & 7);
    const int bcolh = ((lane >> 3) & 1) << 3;

    float c[4][4][4];
#pragma unroll
    for (int mt = 0; mt < 4; mt++)
#pragma unroll
        for (int nt = 0; nt < 4; nt++)
#pragma unroll
            for (int i = 0; i < 4; i++) c[mt][nt][i] = 0.0f;

    const uint32_t stB = HSTAGE * 2;
    gemm_load_stage_h(A, Bt, smBase, smBase + H_TILE * 2, m0, n0, 0, tid);
    asm volatile("cp.async.commit_group;");

    const int NC = DD / 64;
#pragma unroll 1
    for (int ch = 0; ch < NC; ch++) {
        if (ch + 1 < NC) {
            uint32_t db = smBase + ((ch + 1) & 1) * stB;
            gemm_load_stage_h(A, Bt, db, db + H_TILE * 2, m0, n0, (ch + 1) * 64, tid);
            asm volatile("cp.async.commit_group;");
            asm volatile("cp.async.wait_group 1;");
        } else {
            asm volatile("cp.async.wait_group 0;");
        }
        __syncthreads();

        const uint32_t aStage = smBase + ((ch & 1) ? stB : 0u);
        const uint32_t bStage = aStage + H_TILE * 2;

#pragma unroll
        for (int ks = 0; ks < 4; ks++) {
            const int khalf = ks * 16;
            uint32_t a[4][4], b[4][2];
#pragma unroll
            for (int mt = 0; mt < 4; mt++) {
                uint32_t ad = aStage +
                    (uint32_t)(((wm + mt * 16 + lrow) * LDAH + khalf + lsel) * 2);
                ldsm_x4(a[mt][0], a[mt][1], a[mt][2], a[mt][3], ad);
            }
#pragma unroll
            for (int np = 0; np < 2; np++) {
                uint32_t bd = bStage +
                    (uint32_t)(((wn + np * 16 + brow) * LDAH + khalf + bcolh) * 2);
                ldsm_x4(b[2 * np][0], b[2 * np][1], b[2 * np + 1][0], b[2 * np + 1][1], bd);
            }
#pragma unroll
            for (int mt = 0; mt < 4; mt++)
#pragma unroll
                for (int nt = 0; nt < 4; nt++)
                    mma_f16(c[mt][nt], a[mt], b[nt]);
        }
        __syncthreads();
    }

    if (mode == 0) {
        // plain fp32 row-major store
#pragma unroll
        for (int mt = 0; mt < 4; mt++) {
#pragma unroll
            for (int nt = 0; nt < 4; nt++) {
                int row = m0 + wm + mt * 16 + gid;
                int col = n0 + wn + nt * 8 + 2 * tig;
                *(float2*)&Cf[(size_t)row * DD + col] =
                    make_float2(c[mt][nt][0], c[mt][nt][1]);
                *(float2*)&Cf[(size_t)(row + 8) * DD + col] =
                    make_float2(c[mt][nt][2], c[mt][nt][3]);
            }
        }
        return;
    }

    // ---- fused epilogue: stage fp32 tile in smem, then rope / transpose ----
    float* st = (float*)smh;
#pragma unroll
    for (int mt = 0; mt < 4; mt++) {
#pragma unroll
        for (int nt = 0; nt < 4; nt++) {
            int row = wm + mt * 16 + gid;
            int col = wn + nt * 8 + 2 * tig;
            st[row * STLD + col]           = c[mt][nt][0];
            st[row * STLD + col + 1]       = c[mt][nt][1];
            st[(row + 8) * STLD + col]     = c[mt][nt][2];
            st[(row + 8) * STLD + col + 1] = c[mt][nt][3];
        }
    }
    __syncthreads();

    const int b     = m0 >> 11;
    const int sbase = m0 & 2047;
    const int h0    = n0 >> 6;        // first of the 2 heads in this tile

    if (mode != 3) {
        // RoPE on Q or K: out[j] = c[j]*cos - c[j+32]*sin ; out[j+32] = c[j+32]*cos + c[j]*sin
        __half* dstBase = (mode == 1) ? g_Qh : g_Kh;
#pragma unroll 4
        for (int it = 0; it < 32; it++) {
            int i   = tid + it * 256;       // 8192 = 128 rows * 2 heads * 32 pairs
            int j   = i & 31;
            int hl  = (i >> 5) & 1;
            int row = i >> 6;
            int s   = sbase + row;
            float ca = st[row * STLD + hl * 64 + j];
            float cb = st[row * STLD + hl * 64 + j + 32];
            float cs = g_cos[s * 32 + j];
            float sn = g_sin[s * 32 + j];
            __half* d = dstBase + (((size_t)(b * HH + h0 + hl)) * SS + s) * HD;
            d[j]      = __float2half(ca * cs - cb * sn);
            d[j + 32] = __float2half(cb * cs + ca * sn);
        }
    } else {
        // V transpose: g_Vth[b,h,hd,s] = tile[s,hd]
#pragma unroll 4
        for (int it = 0; it < 32; it++) {
            int i  = tid + it * 256;        // 8192 = 128 hd-cols * 64 s-pairs
            int sp = i & 63;
            int s2 = sp * 2;
            int hc = i >> 6;                // 0..127 (2 heads * 64 hd)
            int hl = hc >> 6;
            int hd = hc & 63;
            float v0 = st[s2 * STLD + hc];
            float v1 = st[(s2 + 1) * STLD + hc];
            *(__half2*)&g_Vth[(((size_t)(b * HH + h0 + hl)) * HD + hd) * SS + sbase + s2] =
                __floats2half2_rn(v0, v1);
        }
    }
}

__global__ __launch_bounds__(256) void gemm_qkv() {
    const int n0g = blockIdx.x * 128;
    const int z   = n0g >> 10;
    const int n0  = n0g & 1023;
    const __half* Bt = g_Wh + (size_t)z * DD * DD;
    gemm_body_h(g_xh, Bt, nullptr, z + 1, blockIdx.y * 128, n0);
}

__global__ __launch_bounds__(256) void gemm_out(float* __restrict__ out) {
    gemm_body_h(g_ctxh, g_Wh + (size_t)3 * DD * DD, out, 0,
                blockIdx.y * 128, blockIdx.x * 128);
}

// ============== fp16 tensor-core causal flash attention (unchanged) =========
#define ALDSW 36
#define KV_TILE (64*ALDSW*2)
#define ABUF (2*KV_TILE)
#define ATT_SMEM (2*ABUF*2 + 2*192*4)

__global__ __launch_bounds__(256) void attn_tc() {
    extern __shared__ __half smh[];
    float* Bw = (float*)(smh + 2 * ABUF);

    const int tid  = threadIdx.x;
    const int lane = tid & 31;
    const int w    = tid >> 5;
    const int gid  = lane >> 2;
    const int tig  = lane & 3;

    const int lsel  = (lane >> 4) << 3;
    const int brow  = lsel + (lane & 7);
    const int bcolh = ((lane >> 3) & 1) << 3;

    const int qt = (gridDim.x - 1) - blockIdx.x;
    const int h  = blockIdx.y;
    const int b  = blockIdx.z;
    const int q0 = qt * 128;
    const int ktmax = 2 * qt + 1;

    const __half* Qg  = g_Qh  + (size_t)(b * HH + h) * SS * HD;
    const __half* Kg  = g_Kh  + (size_t)(b * HH + h) * SS * HD;
    const __half* Vtg = g_Vth + (size_t)(b * HH + h) * HD * SS;
    const float* biasH = g_bias + h * SS;

    const uint32_t smBase = (uint32_t)__cvta_generic_to_shared(smh);

    auto prefetch = [&](int kt) {
        const int buf = kt & 1;
        const int k0 = kt * 64;
        uint32_t kb = smBase + (uint32_t)(buf * ABUF) * 2;
        uint32_t vb = kb + KV_TILE * 2;
        const __half* KgT = Kg + (size_t)k0 * HD;
        const __half* VgT = Vtg + k0;
#pragma unroll
        for (int i = 0; i < 2; i++) {
            int s = tid + i * 256;
            int r = s >> 3, cs = s & 7;
            cpasync16(kb + (uint32_t)(r * 144 + cs * 16), KgT + r * HD + cs * 8);
            cpasync16(vb + (uint32_t)(r * 144 + cs * 16), VgT + (size_t)r * SS + cs * 8);
        }
        int dlo = q0 - k0 - 63;
        if (tid < 192) {
            int d = dlo + tid;
            int ok = (d >= 0 && d < SS) ? 4 : 0;
            int dc = d < 0 ? 0 : (d >= SS ? SS - 1 : d);
            uint32_t dst = smBase + (uint32_t)(2 * ABUF) * 2 + (uint32_t)(buf * 192 + tid) * 4;
            asm volatile("cp.async.ca.shared.global [%0], [%1], 4, %2;"
                         :: "r"(dst), "l"(biasH + dc), "r"(ok));
        }
    };

    prefetch(0);
    asm volatile("cp.async.commit_group;");

    const int qr0 = q0 + 16 * w + gid;
    const uint32_t* q0w = (const uint32_t*)(Qg + (size_t)qr0 * HD);
    const uint32_t* q1w = q0w + 8 * HD / 2;
    uint32_t qa[4][4];
#pragma unroll
    for (int kc = 0; kc < 4; kc++) {
        qa[kc][0] = q0w[kc * 8 + tig];
        qa[kc][1] = q1w[kc * 8 + tig];
        qa[kc][2] = q0w[kc * 8 + tig + 4];
        qa[kc][3] = q1w[kc * 8 + tig + 4];
    }

    float o[8][4];
#pragma unroll
    for (int nt = 0; nt < 8; nt++)
#pragma unroll
        for (int i = 0; i < 4; i++) o[nt][i] = 0.0f;
    float m0 = -1e30f, m1 = -1e30f, l0 = 0.0f, l1 = 0.0f;

    for (int kt = 0; kt <= ktmax; kt++) {
        if (kt < ktmax) {
            prefetch(kt + 1);
            asm volatile("cp.async.commit_group;");
            asm volatile("cp.async.wait_group 1;");
        } else {
            asm volatile("cp.async.wait_group 0;");
        }
        __syncthreads();

        const int k0 = kt * 64;
        const bool active = (k0 <= q0 + 16 * w + 15);
        if (active) {
            const uint32_t kStage = smBase + (uint32_t)((kt & 1) * ABUF) * 2;
            const uint32_t vStage = kStage + KV_TILE * 2;
            const float* bw = Bw + (kt & 1) * 192;
            const int dlo = q0 - k0 - 63;

            float s_[8][4];
#pragma unroll
            for (int nt = 0; nt < 8; nt++)
#pragma unroll
                for (int i = 0; i < 4; i++) s_[nt][i] = 0.0f;

#pragma unroll
            for (int kc = 0; kc < 4; kc++) {
                const int khalf = kc * 16;
#pragma unroll
                for (int p = 0; p < 4; p++) {
                    uint32_t kd = kStage +
                        (uint32_t)(((p * 16 + brow) * (ALDSW * 2) + khalf + bcolh) * 2);
                    uint32_t t0, t1, t2, t3;
                    ldsm_x4(t0, t1, t2, t3, kd);
                    uint32_t bf0[2] = { t0, t1 };
                    uint32_t bf1[2] = { t2, t3 };
                    mma_f16(s_[2 * p], qa[kc], bf0);
                    mma_f16(s_[2 * p + 1], qa[kc], bf1);
                }
            }

            const int r0 = qr0, r1 = qr0 + 8;
            const bool needMask = (k0 + 63 > r0);
            float mx0 = m0, mx1 = m1;
#pragma unroll
            for (int nt = 0; nt < 8; nt++) {
                int c0 = k0 + nt * 8 + 2 * tig;
                s_[nt][0] = s_[nt][0] * 0.125f + bw[r0 - c0 - dlo];
                s_[nt][1] = s_[nt][1] * 0.125f + bw[r0 - c0 - 1 - dlo];
                s_[nt][2] = s_[nt][2] * 0.125f + bw[r1 - c0 - dlo];
                s_[nt][3] = s_[nt][3] * 0.125f + bw[r1 - c0 - 1 - dlo];
                if (needMask) {
                    if (c0     > r0) s_[nt][0] = -1e9f;
                    if (c0 + 1 > r0) s_[nt][1] = -1e9f;
                    if (c0     > r1) s_[nt][2] = -1e9f;
                    if (c0 + 1 > r1) s_[nt][3] = -1e9f;
                }
                mx0 = fmaxf(mx0, fmaxf(s_[nt][0], s_[nt][1]));
                mx1 = fmaxf(mx1, fmaxf(s_[nt][2], s_[nt][3]));
            }
            mx0 = fmaxf(mx0, __shfl_xor_sync(0xffffffffu, mx0, 1));
            mx0 = fmaxf(mx0, __shfl_xor_sync(0xffffffffu, mx0, 2));
            mx1 = fmaxf(mx1, __shfl_xor_sync(0xffffffffu, mx1, 1));
            mx1 = fmaxf(mx1, __shfl_xor_sync(0xffffffffu, mx1, 2));

            float corr0 = __expf(m0 - mx0);
            float corr1 = __expf(m1 - mx1);
            m0 = mx0; m1 = mx1;

            uint32_t ph[8][2];
            float ls0 = 0.0f, ls1 = 0.0f;
#pragma unroll
            for (int nt = 0; nt < 8; nt++) {
                float p00 = __expf(s_[nt][0] - mx0);
                float p01 = __expf(s_[nt][1] - mx0);
                float p10 = __expf(s_[nt][2] - mx1);
                float p11 = __expf(s_[nt][3] - mx1);
                ls0 += p00 + p01;
                ls1 += p10 + p11;
                __half2 hp0 = __floats2half2_rn(p00, p01);
                __half2 hp1 = __floats2half2_rn(p10, p11);
                ph[nt][0] = *(uint32_t*)&hp0;
                ph[nt][1] = *(uint32_t*)&hp1;
                o[nt][0] *= corr0; o[nt][1] *= corr0;
                o[nt][2] *= corr1; o[nt][3] *= corr1;
            }
            ls0 += __shfl_xor_sync(0xffffffffu, ls0, 1);
            ls0 += __shfl_xor_sync(0xffffffffu, ls0, 2);
            ls1 += __shfl_xor_sync(0xffffffffu, ls1, 1);
            ls1 += __shfl_xor_sync(0xffffffffu, ls1, 2);
            l0 = l0 * corr0 + ls0;
            l1 = l1 * corr1 + ls1;

#pragma unroll
            for (int kc = 0; kc < 4; kc++) {
                const int khalf = kc * 16;
                uint32_t pa[4] = { ph[2 * kc][0], ph[2 * kc][1],
                                   ph[2 * kc + 1][0], ph[2 * kc + 1][1] };
#pragma unroll
                for (int p = 0; p < 4; p++) {
                    uint32_t vd = vStage +
                        (uint32_t)(((p * 16 + brow) * (ALDSW * 2) + khalf + bcolh) * 2);
                    uint32_t t0, t1, t2, t3;
                    ldsm_x4(t0, t1, t2, t3, vd);
                    uint32_t bf0[2] = { t0, t1 };
                    uint32_t bf1[2] = { t2, t3 };
                    mma_f16(o[2 * p], pa, bf0);
                    mma_f16(o[2 * p + 1], pa, bf1);
                }
            }
        }
        __syncthreads();
    }

    const float inv0 = 1.0f / l0;
    const float inv1 = 1.0f / l1;
    const int hbase = h * HD;
#pragma unroll
    for (int nt = 0; nt < 8; nt++) {
        int c = hbase + nt * 8 + 2 * tig;
        *(__half2*)&g_ctxh[((size_t)b * SS + qr0) * DD + c] =
            __floats2half2_rn(o[nt][0] * inv0, o[nt][1] * inv0);
        *(__half2*)&g_ctxh[((size_t)b * SS + qr0 + 8) * DD + c] =
            __floats2half2_rn(o[nt][2] * inv1, o[nt][3] * inv1);
    }
}

// ---------------- launcher --------------------------------------------------
extern "C" void kernel_launch(void* const* d_in, const int* in_sizes, int n_in,
                              void* d_out, int out_size)
{
    const float* x   = (const float*)d_in[0];
    const float* Wq  = (const float*)d_in[1];
    const float* Wk  = (const float*)d_in[2];
    const float* Wv  = (const float*)d_in[3];
    const float* Wo  = (const float*)d_in[4];
    const float* rel = (const float*)d_in[5];
    float* out = (float*)d_out;

    __half* xh;
    cudaGetSymbolAddress((void**)&xh, g_xh);

    cudaFuncSetAttribute(gemm_qkv, cudaFuncAttributeMaxDynamicSharedMemorySize, GEMM_SMEM);
    cudaFuncSetAttribute(gemm_out, cudaFuncAttributeMaxDynamicSharedMemorySize, GEMM_SMEM);
    cudaFuncSetAttribute(attn_tc, cudaFuncAttributeMaxDynamicSharedMemorySize, ATT_SMEM);

    // 1) setup tables + fp16 conversion of inputs
    bias_table_kernel<<<(HH * SS + 255) / 256, 256>>>(rel);
    rope_table_kernel<<<(SS * 32 + 255) / 256, 256>>>();
    to_half_kernel<<<(MROWS * DD / 4 + 255) / 256, 256>>>(x, xh, MROWS * DD);
    transpose_half_kernel<<<dim3(DD / 32, DD / 32, 4), dim3(32, 8)>>>(Wq, Wk, Wv, Wo);

    // 2) fused QKV projections + RoPE + V-transpose (direct fp16 outputs)
    gemm_qkv<<<dim3(3 * DD / 128, MROWS / 128), 256, GEMM_SMEM>>>();

    // 3) fp16 tensor-core causal attention with bias
    attn_tc<<<dim3(SS / 128, HH, BB), 256, ATT_SMEM>>>();

    // 4) output projection
    gemm_out<<<dim3(DD / 128, MROWS / 128), 256, GEMM_SMEM>>>(out);
}